// round 5
// baseline (speedup 1.0000x reference)
#include <cuda_runtime.h>
#include <math.h>

// Problem shape
#define NB 32
#define CD 512
#define TD 2048
#define KC 512
#define QL 6
#define TT 128                       // tokens per block

#define ELEMS    33554432ULL         // NB*CD*TD
#define IDX_OFF  33554432ULL
#define SCAL_OFF 33947648ULL         // ELEMS + NB*TD*QL

// Device scratch (allocation-free rule: __device__ globals)
__device__ float        g_res  [NB * CD * TD];
__device__ float        g_quant[NB * CD * TD];
__device__ float        g_cbn2f[QL * KC];
__device__ unsigned int g_hist [QL * KC];
__device__ double       g_lossPart[QL * 512];

typedef unsigned long long ull;

// ---- packed f32x2 FMA (FFMA2 is PTX-only; doubles fp32 FMA throughput).
// Per-lane semantics are IEEE fma round-to-nearest, identical to a scalar
// fused-FMA chain — this is what makes the dot bit-match Eigen/cublas
// sequential k-ascending accumulation.
__device__ __forceinline__ ull pack2(float x) {
    ull r; asm("mov.b64 %0, {%1, %1};" : "=l"(r) : "f"(x)); return r;
}
__device__ __forceinline__ void fma2(ull& d, ull a, ull b) {
    asm("fma.rn.f32x2 %0, %1, %2, %0;" : "+l"(d) : "l"(a), "l"(b));
}
__device__ __forceinline__ void unpack2(ull v, float& lo, float& hi) {
    asm("mov.b64 {%0, %1}, %2;" : "=f"(lo), "=f"(hi) : "l"(v));
}

// ---- prep: zero histogram, sequential-fp32 codebook norms.
// One thread per code row: cbn = ((fl(v0^2) + fl(v1^2)) + ...) ascending c —
// matches XLA's elementwise-square-then-sequential-reduce rounding.
__global__ void vq_prep(const float* cb) {
    int gid = blockIdx.x * 256 + threadIdx.x;
    if (gid < QL * KC) {
        g_hist[gid] = 0u;
        const float* row = cb + (size_t)gid * CD;
        float s = 0.0f;
        for (int c = 0; c < CD; c++) {
            float v = row[c];
            s = __fadd_rn(s, __fmul_rn(v, v));
        }
        g_cbn2f[gid] = s;
    }
}

// ---- shared memory union (phases serialized by __syncthreads) ----
struct SG { float cbs[32][68]; float ress[32][TT]; };   // GEMM tiles (25.1 KB)
struct SR { float d1[8][TT]; int k1[8][TT]; };          // argmin reduce (8 KB)
struct SS { float cbS[TT][65]; };                       // gather stage (33.3 KB)
union __align__(16) SU { SG g; SR r; SS s; };

// ---- fused per-layer kernel: S1 + GEMM + argmin + gather + update ----
__global__ void __launch_bounds__(256, 2) vq_layer(
    const float* x, const float* cb, float* out, int q)
{
    __shared__ SU sm;
    __shared__ float  sS1[TT];
    __shared__ int    sK[TT];
    __shared__ double sL[8];

    const int tid  = threadIdx.x;
    const int lane = tid & 31;
    const int warp = tid >> 5;
    const int n    = blockIdx.y;
    const int t0   = blockIdx.x * TT;
    const float* resin = (q == 0) ? x : g_res;
    const float* cbq   = cb + (size_t)q * KC * CD;
    const float* cbnF  = g_cbn2f + q * KC;
    const size_t base  = (size_t)n * CD * TD;

    // ---- S1 per token: strict sequential fp32, c ascending ----
    if (tid < TT) {
        const float* p = resin + base + t0 + tid;
        float s = 0.0f;
        for (int c = 0; c < CD; c++) {
            float v = p[(size_t)c * TD];
            s = __fadd_rn(s, __fmul_rn(v, v));
        }
        sS1[tid] = s;
    }
    __syncthreads();

    // per-thread running argmin over 4 tokens (tokens lane*4 + {0..3})
    float bd[4]; int bk[4];
#pragma unroll
    for (int t = 0; t < 4; t++) { bd[t] = __int_as_float(0x7f800000); bk[t] = 0; }

    // ---- GEMM: dot(t,k) as one sequential fused-FMA chain over c=0..511 ----
    for (int kt = 0; kt < 8; kt++) {
        ull acc[8][2];
#pragma unroll
        for (int j = 0; j < 8; j++) { acc[j][0] = 0ull; acc[j][1] = 0ull; }

        for (int cc = 0; cc < 16; cc++) {
            const int c0 = cc * 32;
            // codebook tile [64k x 32c] -> cbs[c][k] (transposed, padded)
#pragma unroll
            for (int m = 0; m < 2; m++) {
                int f = m * 256 + tid;           // float4 index 0..511
                int row = f >> 3, c4 = f & 7;
                float4 v = *(const float4*)(cbq + (size_t)(kt * 64 + row) * CD + c0 + c4 * 4);
                sm.g.cbs[c4 * 4 + 0][row] = v.x;
                sm.g.cbs[c4 * 4 + 1][row] = v.y;
                sm.g.cbs[c4 * 4 + 2][row] = v.z;
                sm.g.cbs[c4 * 4 + 3][row] = v.w;
            }
            // residual tile [32c x 128t]
#pragma unroll
            for (int m = 0; m < 4; m++) {
                int f = m * 256 + tid;           // float4 index 0..1023
                int row = f >> 5, t4 = f & 31;
                *(float4*)&sm.g.ress[row][t4 * 4] =
                    *(const float4*)(resin + base + (size_t)(c0 + row) * TD + t0 + t4 * 4);
            }
            __syncthreads();

#pragma unroll 8
            for (int c = 0; c < 32; c++) {
                float4 ka = *(const float4*)&sm.g.cbs[c][warp * 8];
                float4 kb = *(const float4*)&sm.g.cbs[c][warp * 8 + 4];
                ull a0 = pack2(ka.x), a1 = pack2(ka.y), a2 = pack2(ka.z), a3 = pack2(ka.w);
                ull a4 = pack2(kb.x), a5 = pack2(kb.y), a6 = pack2(kb.z), a7 = pack2(kb.w);
                ulonglong2 b = *(const ulonglong2*)&sm.g.ress[c][lane * 4];
                fma2(acc[0][0], a0, b.x); fma2(acc[0][1], a0, b.y);
                fma2(acc[1][0], a1, b.x); fma2(acc[1][1], a1, b.y);
                fma2(acc[2][0], a2, b.x); fma2(acc[2][1], a2, b.y);
                fma2(acc[3][0], a3, b.x); fma2(acc[3][1], a3, b.y);
                fma2(acc[4][0], a4, b.x); fma2(acc[4][1], a4, b.y);
                fma2(acc[5][0], a5, b.x); fma2(acc[5][1], a5, b.y);
                fma2(acc[6][0], a6, b.x); fma2(acc[6][1], a6, b.y);
                fma2(acc[7][0], a7, b.x); fma2(acc[7][1], a7, b.y);
            }
            __syncthreads();
        }
        // epilogue: dist = fl(fl(S1 - 2*dot) + cbn) — reference rounding chain
#pragma unroll
        for (int j = 0; j < 8; j++) {
            int k = kt * 64 + warp * 8 + j;
            float cbn = __ldg(&cbnF[k]);
#pragma unroll
            for (int p = 0; p < 2; p++) {
                float lo, hi; unpack2(acc[j][p], lo, hi);
                int ta = p * 2, tb = p * 2 + 1;
                float d0 = __fadd_rn(__fsub_rn(sS1[lane * 4 + ta], __fmul_rn(2.0f, lo)), cbn);
                float d1 = __fadd_rn(__fsub_rn(sS1[lane * 4 + tb], __fmul_rn(2.0f, hi)), cbn);
                if (d0 < bd[ta] || (d0 == bd[ta] && k < bk[ta])) { bd[ta] = d0; bk[ta] = k; }
                if (d1 < bd[tb] || (d1 == bd[tb] && k < bk[tb])) { bd[tb] = d1; bk[tb] = k; }
            }
        }
    }

    // ---- cross-warp argmin (first-index tie break = jnp.argmax(-dist)) ----
#pragma unroll
    for (int t = 0; t < 4; t++) {
        int tl = lane * 4 + t;
        sm.r.d1[warp][tl] = bd[t];
        sm.r.k1[warp][tl] = bk[t];
    }
    __syncthreads();
    if (tid < TT) {
        float D = __int_as_float(0x7f800000); int K = 0;
#pragma unroll
        for (int w = 0; w < 8; w++) {
            float d = sm.r.d1[w][tid]; int k = sm.r.k1[w][tid];
            if (d < D || (d == D && k < K)) { D = d; K = k; }
        }
        sK[tid] = K;
        out[IDX_OFF + ((size_t)(n * TD + t0 + tid)) * QL + q] = (float)K;
        atomicAdd(&g_hist[q * KC + K], 1u);
    }
    __syncthreads();

    // ---- gather + elementwise update (reference fp32 rounding chain) ----
    const int tl    = tid & 127;
    const int chalf = tid >> 7;
    double lacc = 0.0;
    for (int ch = 0; ch < 8; ch++) {
        const int c0 = ch * 64;
        __syncthreads();                        // protect cbS reuse across chunks
        // stage 128 codeword slices [128t x 64c] (bank-conflict-free, pad 65)
        for (int u = 0; u < 16; u++) {
            int tt = warp * 16 + u;
            const float* cr = cbq + (size_t)sK[tt] * CD + c0;
            sm.s.cbS[tt][lane]      = cr[lane];
            sm.s.cbS[tt][lane + 32] = cr[lane + 32];
        }
        __syncthreads();
#pragma unroll 4
        for (int it = 0; it < 32; it++) {
            int c = c0 + it * 2 + chalf;
            size_t off = base + (size_t)c * TD + t0 + tl;
            float xf = resin[off];
            float xd = sm.s.cbS[tl][c - c0];
            float qv = __fadd_rn(xf, __fsub_rn(xd, xf));   // straight-through
            float df = __fsub_rn(xf, xd);                   // commit diff
            lacc += (double)__fmul_rn(df, df);
            if (q < QL - 1) g_res[off] = __fsub_rn(xf, qv); // residual update
            float qa = (q == 0) ? qv : __fadd_rn(g_quant[off], qv);
            if (q < QL - 1) g_quant[off] = qa;
            else            out[off] = qa;                  // final quantized_out
        }
    }

    // ---- deterministic block loss partial ----
    for (int o = 16; o > 0; o >>= 1) lacc += __shfl_down_sync(0xffffffffu, lacc, o);
    if (lane == 0) sL[warp] = lacc;
    __syncthreads();
    if (tid == 0) {
        double s = 0.0;
        for (int w = 0; w < 8; w++) s += sL[w];
        g_lossPart[q * 512 + blockIdx.y * 16 + blockIdx.x] = s;
    }
}

// ---- scalars: commit loss mean + perplexity (parallel, deterministic) ----
__global__ void vq_final(float* out) {
    __shared__ double sPerp[QL], sLoss[QL];
    int warp = threadIdx.x >> 5, lane = threadIdx.x & 31;
    if (warp < QL) {
        int q = warp;
        double ls = 0.0;
        for (int b = lane; b < 512; b += 32) ls += g_lossPart[q * 512 + b];
        double ent = 0.0;
        for (int k = lane; k < KC; k += 32) {
            float cnt  = (float)g_hist[q * KC + k];
            float prob = cnt / 65536.0f;
            ent += (double)prob * log((double)prob + 1e-7);
        }
        for (int o = 16; o > 0; o >>= 1) {
            ls  += __shfl_down_sync(0xffffffffu, ls, o);
            ent += __shfl_down_sync(0xffffffffu, ent, o);
        }
        if (lane == 0) { sLoss[q] = ls / (double)ELEMS; sPerp[q] = exp(-ent); }
    }
    __syncthreads();
    if (threadIdx.x == 0) {
        double lsum = 0.0, psum = 0.0;
        for (int q = 0; q < QL; q++) { lsum += sLoss[q]; psum += sPerp[q]; }
        out[SCAL_OFF]     = (float)(lsum / (double)QL);
        out[SCAL_OFF + 1] = (float)(psum / (double)QL);
    }
}

extern "C" void kernel_launch(void* const* d_in, const int* in_sizes, int n_in,
                              void* d_out, int out_size) {
    const float* x  = (const float*)d_in[0];   // [32, 512, 2048] f32
    const float* cb = (const float*)d_in[1];   // [6, 512, 512]  f32
    float* out = (float*)d_out;

    vq_prep<<<12, 256>>>(cb);
    dim3 grid(TD / TT, NB);                    // (16, 32) = 512 blocks
    for (int q = 0; q < QL; q++)
        vq_layer<<<grid, 256>>>(x, cb, out, q);
    vq_final<<<1, QL * 32>>>(out);
}

// round 6
// speedup vs baseline: 1.0444x; 1.0444x over previous
#include <cuda_runtime.h>
#include <math.h>

// Problem shape
#define NB 32
#define CD 512
#define TD 2048
#define KC 512
#define QL 6
#define TT 128                       // tokens per block

#define ELEMS    33554432ULL         // NB*CD*TD
#define IDX_OFF  33554432ULL
#define SCAL_OFF 33947648ULL         // ELEMS + NB*TD*QL

// Pipeline geometry
#define NSTAGE    3
#define CB_BYTES  (64 * 32 * 4)                  // 8 KB  codebook tile [64k][32c]
#define RS_BYTES  (32 * 128 * 4)                 // 16 KB residual tile [32c][128t]
#define STG_BYTES (CB_BYTES + RS_BYTES)          // 24 KB per stage
#define DYN_BYTES (NSTAGE * STG_BYTES)           // 73728 B dynamic smem

// Device scratch (allocation-free rule: __device__ globals)
__device__ float        g_res  [NB * CD * TD];
__device__ float        g_quant[NB * CD * TD];
__device__ float        g_cbn2f[QL * KC];
__device__ unsigned int g_hist [QL * KC];
__device__ double       g_lossPart[QL * 512];

typedef unsigned long long ull;

// ---- packed f32x2 FMA (FFMA2 is PTX-only; per-lane IEEE fma => the dot is a
// single sequential fused-FMA chain, bit-matching the reference backend) ----
__device__ __forceinline__ ull pack2(float x) {
    ull r; asm("mov.b64 %0, {%1, %1};" : "=l"(r) : "f"(x)); return r;
}
__device__ __forceinline__ void fma2(ull& d, ull a, ull b) {
    asm("fma.rn.f32x2 %0, %1, %2, %0;" : "+l"(d) : "l"(a), "l"(b));
}
__device__ __forceinline__ void unpack2(ull v, float& lo, float& hi) {
    asm("mov.b64 {%0, %1}, %2;" : "=f"(lo), "=f"(hi) : "l"(v));
}

// ---- cp.async helpers ----
__device__ __forceinline__ void cpa16(unsigned dst, const float* src) {
    asm volatile("cp.async.cg.shared.global [%0], [%1], 16;" :: "r"(dst), "l"(src));
}
__device__ __forceinline__ void cp_commit() {
    asm volatile("cp.async.commit_group;");
}
template<int N> __device__ __forceinline__ void cp_wait() {
    asm volatile("cp.async.wait_group %0;" :: "n"(N));
}

// ---- prep: zero histogram, sequential-fp32 codebook norms (reference chain) ----
__global__ void vq_prep(const float* cb) {
    int gid = blockIdx.x * 256 + threadIdx.x;
    if (gid < QL * KC) {
        g_hist[gid] = 0u;
        const float* row = cb + (size_t)gid * CD;
        float s = 0.0f;
        for (int c = 0; c < CD; c++) {
            float v = row[c];
            s = __fadd_rn(s, __fmul_rn(v, v));
        }
        g_cbn2f[gid] = s;
    }
}

// chunk prefetch: chunk ci covers k rows [kt*64,+64), c cols [cc*32,+32)
__device__ __forceinline__ void prefetch_chunk(
    unsigned sb, int ci, const float* cbq, const float* resin,
    size_t base, int t0, int tid)
{
    const int kt = ci >> 4, cc = ci & 15;
    const int c0 = cc * 32, k0 = kt * 64;
    const unsigned st = sb + (unsigned)((ci % NSTAGE) * STG_BYTES);
    // codebook tile: 512 x 16B, untransposed [k][c]
#pragma unroll
    for (int m = 0; m < 2; m++) {
        int idx = m * 256 + tid;
        int row = idx >> 3, seg = idx & 7;
        cpa16(st + row * 128 + seg * 16,
              cbq + (size_t)(k0 + row) * CD + c0 + seg * 4);
    }
    // residual tile: 1024 x 16B, [c][t]
#pragma unroll
    for (int m = 0; m < 4; m++) {
        int idx = m * 256 + tid;
        int row = idx >> 5, seg = idx & 31;
        cpa16(st + CB_BYTES + row * 512 + seg * 16,
              resin + base + (size_t)(c0 + row) * TD + t0 + seg * 4);
    }
}

// ---- fused per-layer kernel: S1 + pipelined GEMM + argmin + gather + update ----
__global__ void __launch_bounds__(256, 2) vq_layer(
    const float* x, const float* cb, float* out, int q)
{
    extern __shared__ char dyn[];
    __shared__ float  sS1[TT];
    __shared__ int    sK[TT];
    __shared__ double sL[8];

    const unsigned sb = (unsigned)__cvta_generic_to_shared(dyn);
    const int tid  = threadIdx.x;
    const int lane = tid & 31;
    const int warp = tid >> 5;
    const int n    = blockIdx.y;
    const int t0   = blockIdx.x * TT;
    const float* resin = (q == 0) ? x : g_res;
    const float* cbq   = cb + (size_t)q * KC * CD;
    const float* cbnF  = g_cbn2f + q * KC;
    const size_t base  = (size_t)n * CD * TD;

    // prologue: start prefetch of chunks 0,1 before anything else
    prefetch_chunk(sb, 0, cbq, resin, base, t0, tid); cp_commit();
    prefetch_chunk(sb, 1, cbq, resin, base, t0, tid); cp_commit();

    // ---- S1 per token (strict sequential fp32, c ascending) — overlaps prefetch ----
    if (tid < TT) {
        const float* p = resin + base + t0 + tid;
        float s = 0.0f;
        for (int c = 0; c < CD; c++) {
            float v = p[(size_t)c * TD];
            s = __fadd_rn(s, __fmul_rn(v, v));
        }
        sS1[tid] = s;
    }

    // per-thread running argmin over 4 tokens (tokens lane*4 + {0..3})
    float bd[4]; int bk[4];
#pragma unroll
    for (int t = 0; t < 4; t++) { bd[t] = __int_as_float(0x7f800000); bk[t] = 0; }

    ull acc[8][2];
#pragma unroll
    for (int j = 0; j < 8; j++) { acc[j][0] = 0ull; acc[j][1] = 0ull; }

    // ---- pipelined GEMM mainloop: 128 chunks (8 kt x 16 cc) ----
    for (int ci = 0; ci < 128; ci++) {
        cp_wait<1>();                // stage ci%3 data landed (this thread's copies)
        __syncthreads();             // all threads' copies visible; prev stage free
        if (ci + 2 < 128) prefetch_chunk(sb, ci + 2, cbq, resin, base, t0, tid);
        cp_commit();

        const float* cbk = (const float*)(dyn + (ci % NSTAGE) * STG_BYTES);
        const float* rss = (const float*)(dyn + (ci % NSTAGE) * STG_BYTES + CB_BYTES);

        // compute chunk: 32 c as 16 pairs; per (t,k) chain stays c-ascending
#pragma unroll 4
        for (int cp = 0; cp < 16; cp++) {
            float2 a[8];
#pragma unroll
            for (int j = 0; j < 8; j++)
                a[j] = *(const float2*)&cbk[(warp * 8 + j) * 32 + cp * 2]; // broadcast
            ulonglong2 b0 = *(const ulonglong2*)&rss[(cp * 2)     * 128 + lane * 4];
            ulonglong2 b1 = *(const ulonglong2*)&rss[(cp * 2 + 1) * 128 + lane * 4];
#pragma unroll
            for (int j = 0; j < 8; j++) {
                ull ax = pack2(a[j].x), ay = pack2(a[j].y);
                fma2(acc[j][0], ax, b0.x); fma2(acc[j][1], ax, b0.y);
                fma2(acc[j][0], ay, b1.x); fma2(acc[j][1], ay, b1.y);
            }
        }

        // end of a kt pass: fold into argmin, reset accumulators
        if ((ci & 15) == 15) {
            int kt = ci >> 4;
#pragma unroll
            for (int j = 0; j < 8; j++) {
                int k = kt * 64 + warp * 8 + j;
                float cbn = __ldg(&cbnF[k]);
#pragma unroll
                for (int p = 0; p < 2; p++) {
                    float lo, hi; unpack2(acc[j][p], lo, hi);
                    int ta = p * 2, tb = p * 2 + 1;
                    float d0 = __fadd_rn(__fsub_rn(sS1[lane * 4 + ta], __fmul_rn(2.0f, lo)), cbn);
                    float d1 = __fadd_rn(__fsub_rn(sS1[lane * 4 + tb], __fmul_rn(2.0f, hi)), cbn);
                    if (d0 < bd[ta] || (d0 == bd[ta] && k < bk[ta])) { bd[ta] = d0; bk[ta] = k; }
                    if (d1 < bd[tb] || (d1 == bd[tb] && k < bk[tb])) { bd[tb] = d1; bk[tb] = k; }
                    acc[j][p] = 0ull;
                }
            }
        }
    }
    cp_wait<0>();
    __syncthreads();

    // ---- cross-warp argmin (first-index tie break = jnp.argmax(-dist)) ----
    float* rd1 = (float*)dyn;                 // [8][128]
    int*   rk1 = (int*)(dyn + 4096);          // [8][128]
#pragma unroll
    for (int t = 0; t < 4; t++) {
        int tl = lane * 4 + t;
        rd1[warp * TT + tl] = bd[t];
        rk1[warp * TT + tl] = bk[t];
    }
    __syncthreads();
    if (tid < TT) {
        float D = __int_as_float(0x7f800000); int K = 0;
#pragma unroll
        for (int w = 0; w < 8; w++) {
            float d = rd1[w * TT + tid]; int k = rk1[w * TT + tid];
            if (d < D || (d == D && k < K)) { D = d; K = k; }
        }
        sK[tid] = K;
        out[IDX_OFF + ((size_t)(n * TD + t0 + tid)) * QL + q] = (float)K;
        atomicAdd(&g_hist[q * KC + K], 1u);
    }
    __syncthreads();

    // ---- gather + elementwise update (reference fp32 rounding chain) ----
    float* cbS = (float*)dyn;                 // [128][65] staged codewords
    const int tl    = tid & 127;
    const int chalf = tid >> 7;
    double lacc = 0.0;
    for (int ch = 0; ch < 8; ch++) {
        const int c0 = ch * 64;
        __syncthreads();                      // protect cbS reuse across chunks
        for (int u = 0; u < 16; u++) {
            int tt = warp * 16 + u;
            const float* cr = cbq + (size_t)sK[tt] * CD + c0;
            cbS[tt * 65 + lane]      = cr[lane];
            cbS[tt * 65 + lane + 32] = cr[lane + 32];
        }
        __syncthreads();
#pragma unroll 4
        for (int it = 0; it < 32; it++) {
            int c = c0 + it * 2 + chalf;
            size_t off = base + (size_t)c * TD + t0 + tl;
            float xf = resin[off];
            float xd = cbS[tl * 65 + (c - c0)];
            float qv = __fadd_rn(xf, __fsub_rn(xd, xf));   // straight-through
            float df = __fsub_rn(xf, xd);                   // commit diff
            lacc += (double)__fmul_rn(df, df);
            if (q < QL - 1) g_res[off] = __fsub_rn(xf, qv); // residual update
            float qa = (q == 0) ? qv : __fadd_rn(g_quant[off], qv);
            if (q < QL - 1) g_quant[off] = qa;
            else            out[off] = qa;                  // final quantized_out
        }
    }

    // ---- deterministic block loss partial ----
    for (int o = 16; o > 0; o >>= 1) lacc += __shfl_down_sync(0xffffffffu, lacc, o);
    if (lane == 0) sL[warp] = lacc;
    __syncthreads();
    if (tid == 0) {
        double s = 0.0;
        for (int w = 0; w < 8; w++) s += sL[w];
        g_lossPart[q * 512 + blockIdx.y * 16 + blockIdx.x] = s;
    }
}

// ---- scalars: commit loss mean + perplexity (parallel, deterministic) ----
__global__ void vq_final(float* out) {
    __shared__ double sPerp[QL], sLoss[QL];
    int warp = threadIdx.x >> 5, lane = threadIdx.x & 31;
    if (warp < QL) {
        int q = warp;
        double ls = 0.0;
        for (int b = lane; b < 512; b += 32) ls += g_lossPart[q * 512 + b];
        double ent = 0.0;
        for (int k = lane; k < KC; k += 32) {
            float cnt  = (float)g_hist[q * KC + k];
            float prob = cnt / 65536.0f;
            ent += (double)prob * log((double)prob + 1e-7);
        }
        for (int o = 16; o > 0; o >>= 1) {
            ls  += __shfl_down_sync(0xffffffffu, ls, o);
            ent += __shfl_down_sync(0xffffffffu, ent, o);
        }
        if (lane == 0) { sLoss[q] = ls / (double)ELEMS; sPerp[q] = exp(-ent); }
    }
    __syncthreads();
    if (threadIdx.x == 0) {
        double lsum = 0.0, psum = 0.0;
        for (int q = 0; q < QL; q++) { lsum += sLoss[q]; psum += sPerp[q]; }
        out[SCAL_OFF]     = (float)(lsum / (double)QL);
        out[SCAL_OFF + 1] = (float)(psum / (double)QL);
    }
}

extern "C" void kernel_launch(void* const* d_in, const int* in_sizes, int n_in,
                              void* d_out, int out_size) {
    const float* x  = (const float*)d_in[0];   // [32, 512, 2048] f32
    const float* cb = (const float*)d_in[1];   // [6, 512, 512]  f32
    float* out = (float*)d_out;

    cudaFuncSetAttribute(vq_layer,
                         cudaFuncAttributeMaxDynamicSharedMemorySize, DYN_BYTES);

    vq_prep<<<12, 256>>>(cb);
    dim3 grid(TD / TT, NB);                    // (16, 32) = 512 blocks
    for (int q = 0; q < QL; q++)
        vq_layer<<<grid, 256, DYN_BYTES>>>(x, cb, out, q);
    vq_final<<<1, QL * 32>>>(out);
}

// round 8
// speedup vs baseline: 1.1001x; 1.0533x over previous
#include <cuda_runtime.h>
#include <math.h>

// Problem shape
#define NB 32
#define CD 512
#define TD 2048
#define KC 512
#define QL 6
#define TT 128                       // tokens per block

#define ELEMS    33554432ULL         // NB*CD*TD
#define IDX_OFF  33554432ULL
#define SCAL_OFF 33947648ULL         // ELEMS + NB*TD*QL

// Pipeline geometry: chunk = [128k x 32c] cb tile + [32c x 128t] res tile
#define NSTAGE    3
#define CB_BYTES  (128 * 32 * 4)                 // 16 KB codebook tile [k][c]
#define RS_BYTES  (32 * 128 * 4)                 // 16 KB residual tile [c][t]
#define STG_BYTES (CB_BYTES + RS_BYTES)          // 32 KB per stage
#define DYN_BYTES (NSTAGE * STG_BYTES)           // 96 KB dynamic smem
#define NCHUNK    64                             // 4 kt passes x 16 c chunks

// Device scratch (allocation-free rule: __device__ globals)
__device__ float        g_res  [NB * CD * TD];
__device__ float        g_quant[NB * CD * TD];
__device__ float        g_cbn2f[QL * KC];
__device__ unsigned int g_hist [QL * KC];
__device__ double       g_lossPart[QL * 512];

typedef unsigned long long ull;

// ---- packed f32x2 FMA (FFMA2 is PTX-only; per-lane IEEE fma => each dot is a
// single sequential fused-FMA chain, bit-matching the reference backend) ----
__device__ __forceinline__ ull pack2(float x) {
    ull r; asm("mov.b64 %0, {%1, %1};" : "=l"(r) : "f"(x)); return r;
}
__device__ __forceinline__ void fma2(ull& d, ull a, ull b) {
    asm("fma.rn.f32x2 %0, %1, %2, %0;" : "+l"(d) : "l"(a), "l"(b));
}
__device__ __forceinline__ void unpack2(ull v, float& lo, float& hi) {
    asm("mov.b64 {%0, %1}, %2;" : "=f"(lo), "=f"(hi) : "l"(v));
}

// ---- cp.async helpers ----
__device__ __forceinline__ void cpa16(unsigned dst, const float* src) {
    asm volatile("cp.async.cg.shared.global [%0], [%1], 16;" :: "r"(dst), "l"(src));
}
__device__ __forceinline__ void cp_commit() {
    asm volatile("cp.async.commit_group;");
}
template<int N> __device__ __forceinline__ void cp_wait() {
    asm volatile("cp.async.wait_group %0;" :: "n"(N));
}

// ---- prep: zero histogram, sequential-fp32 codebook norms (reference chain) ----
__global__ void vq_prep(const float* cb) {
    int gid = blockIdx.x * 256 + threadIdx.x;
    if (gid < QL * KC) {
        g_hist[gid] = 0u;
        const float* row = cb + (size_t)gid * CD;
        float s = 0.0f;
        for (int c = 0; c < CD; c++) {
            float v = row[c];
            s = __fadd_rn(s, __fmul_rn(v, v));
        }
        g_cbn2f[gid] = s;
    }
}

// chunk ci: kt = ci>>4 (k rows [kt*128,+128)), cc = ci&15 (c cols [cc*32,+32))
__device__ __forceinline__ void prefetch_chunk(
    unsigned sb, int ci, const float* cbq, const float* resin,
    size_t base, int t0, int tid)
{
    const int kt = ci >> 4, cc = ci & 15;
    const int c0 = cc * 32, k0 = kt * 128;
    const unsigned st = sb + (unsigned)((ci % NSTAGE) * STG_BYTES);
    // codebook tile: 1024 x 16B, [k][c] (row = 32 floats = 128 B)
#pragma unroll
    for (int m = 0; m < 4; m++) {
        int idx = m * 256 + tid;
        int row = idx >> 3, seg = idx & 7;
        cpa16(st + row * 128 + seg * 16,
              cbq + (size_t)(k0 + row) * CD + c0 + seg * 4);
    }
    // residual tile: 1024 x 16B, [c][t]
#pragma unroll
    for (int m = 0; m < 4; m++) {
        int idx = m * 256 + tid;
        int row = idx >> 5, seg = idx & 31;
        cpa16(st + CB_BYTES + row * 512 + seg * 16,
              resin + base + (size_t)(c0 + row) * TD + t0 + seg * 4);
    }
}

// ---- fused per-layer kernel: S1 + pipelined GEMM + argmin + gather + update ----
__global__ void __launch_bounds__(256, 2) vq_layer(
    const float* x, const float* cb, float* out, int q)
{
    extern __shared__ char dyn[];
    __shared__ float  sS1[TT];
    __shared__ int    sK[TT];
    __shared__ double sL[8];

    const unsigned sb = (unsigned)__cvta_generic_to_shared(dyn);
    const int tid  = threadIdx.x;
    const int lane = tid & 31;
    const int warp = tid >> 5;
    const int kg   = tid >> 4;    // 16 k-groups of 8 rows
    const int tg   = tid & 15;    // 16 t-groups; tokens tg*4..+3 and 64+tg*4..+3
    const int n    = blockIdx.y;
    const int t0   = blockIdx.x * TT;
    const float* resin = (q == 0) ? x : g_res;
    const float* cbq   = cb + (size_t)q * KC * CD;
    const float* cbnF  = g_cbn2f + q * KC;
    const size_t base  = (size_t)n * CD * TD;

    // prologue: prefetch chunks 0,1
    prefetch_chunk(sb, 0, cbq, resin, base, t0, tid); cp_commit();
    prefetch_chunk(sb, 1, cbq, resin, base, t0, tid); cp_commit();

    // ---- S1 per token (strict sequential fp32, c ascending) ----
    if (tid < TT) {
        const float* p = resin + base + t0 + tid;
        float s = 0.0f;
        for (int c = 0; c < CD; c++) {
            float v = p[(size_t)c * TD];
            s = __fadd_rn(s, __fmul_rn(v, v));
        }
        sS1[tid] = s;
    }

    // per-thread argmin over 8 tokens (slot s -> token tloc(s))
    float bd[8]; int bk[8];
#pragma unroll
    for (int s = 0; s < 8; s++) { bd[s] = __int_as_float(0x7f800000); bk[s] = 0; }

    ull acc[8][4];
#pragma unroll
    for (int j = 0; j < 8; j++)
#pragma unroll
        for (int p = 0; p < 4; p++) acc[j][p] = 0ull;

    // ---- pipelined GEMM mainloop: 64 chunks (4 kt x 16 cc) ----
    for (int ci = 0; ci < NCHUNK; ci++) {
        cp_wait<1>();
        __syncthreads();
        if (ci + 2 < NCHUNK) prefetch_chunk(sb, ci + 2, cbq, resin, base, t0, tid);
        cp_commit();

        const float* cbk = (const float*)(dyn + (ci % NSTAGE) * STG_BYTES);
        const float* rss = (const float*)(dyn + (ci % NSTAGE) * STG_BYTES + CB_BYTES);

#pragma unroll 4
        for (int cp = 0; cp < 16; cp++) {
            // b operands: two dense 16-lane t-blocks per c (2 wavefronts each)
            ulonglong2 c0a = *(const ulonglong2*)&rss[(cp * 2)     * 128      + tg * 4];
            ulonglong2 c0b = *(const ulonglong2*)&rss[(cp * 2)     * 128 + 64 + tg * 4];
            ulonglong2 c1a = *(const ulonglong2*)&rss[(cp * 2 + 1) * 128      + tg * 4];
            ulonglong2 c1b = *(const ulonglong2*)&rss[(cp * 2 + 1) * 128 + 64 + tg * 4];
#pragma unroll
            for (int j = 0; j < 8; j++) {
                float2 av = *(const float2*)&cbk[(kg * 8 + j) * 32 + cp * 2];
                ull ax = pack2(av.x), ay = pack2(av.y);
                // c ascending per accumulator: c0 then c1
                fma2(acc[j][0], ax, c0a.x); fma2(acc[j][1], ax, c0a.y);
                fma2(acc[j][2], ax, c0b.x); fma2(acc[j][3], ax, c0b.y);
                fma2(acc[j][0], ay, c1a.x); fma2(acc[j][1], ay, c1a.y);
                fma2(acc[j][2], ay, c1b.x); fma2(acc[j][3], ay, c1b.y);
            }
        }

        // end of a kt pass: fold into argmin, reset accumulators
        if ((ci & 15) == 15) {
            int kt = ci >> 4;
#pragma unroll
            for (int j = 0; j < 8; j++) {
                int k = kt * 128 + kg * 8 + j;
                float cbn = __ldg(&cbnF[k]);
#pragma unroll
                for (int p = 0; p < 4; p++) {
                    float lo, hi; unpack2(acc[j][p], lo, hi);
                    int s0 = p * 2, s1 = p * 2 + 1;
                    int ta = (p < 2) ? (tg * 4 + p * 2)     : (64 + tg * 4 + (p - 2) * 2);
                    float d0 = __fadd_rn(__fsub_rn(sS1[ta],     __fmul_rn(2.0f, lo)), cbn);
                    float d1 = __fadd_rn(__fsub_rn(sS1[ta + 1], __fmul_rn(2.0f, hi)), cbn);
                    if (d0 < bd[s0] || (d0 == bd[s0] && k < bk[s0])) { bd[s0] = d0; bk[s0] = k; }
                    if (d1 < bd[s1] || (d1 == bd[s1] && k < bk[s1])) { bd[s1] = d1; bk[s1] = k; }
                    acc[j][p] = 0ull;
                }
            }
        }
    }
    cp_wait<0>();
    __syncthreads();

    // ---- cross-thread argmin over 16 kg rows (explicit k compare => exact
    //      first-index tie break regardless of scan order) ----
    float* rd1 = (float*)dyn;                 // [16][128]
    int*   rk1 = (int*)(dyn + 8192);          // [16][128]
#pragma unroll
    for (int s = 0; s < 8; s++) {
        int tloc = (s < 4) ? (tg * 4 + s) : (64 + tg * 4 + (s - 4));
        rd1[kg * TT + tloc] = bd[s];
        rk1[kg * TT + tloc] = bk[s];
    }
    __syncthreads();
    if (tid < TT) {
        float D = __int_as_float(0x7f800000); int K = 0;
#pragma unroll
        for (int g = 0; g < 16; g++) {
            float d = rd1[g * TT + tid]; int k = rk1[g * TT + tid];
            if (d < D || (d == D && k < K)) { D = d; K = k; }
        }
        sK[tid] = K;
        out[IDX_OFF + ((size_t)(n * TD + t0 + tid)) * QL + q] = (float)K;
        atomicAdd(&g_hist[q * KC + K], 1u);
    }
    __syncthreads();

    // ---- gather + elementwise update (reference fp32 rounding chain) ----
    float* cbS = (float*)dyn;                 // [128][65] staged codewords
    const int tl    = tid & 127;
    const int chalf = tid >> 7;
    double lacc = 0.0;
    for (int ch = 0; ch < 8; ch++) {
        const int c0 = ch * 64;
        __syncthreads();                      // protect cbS reuse across chunks
        for (int u = 0; u < 16; u++) {
            int tt = warp * 16 + u;
            const float* cr = cbq + (size_t)sK[tt] * CD + c0;
            cbS[tt * 65 + lane]      = cr[lane];
            cbS[tt * 65 + lane + 32] = cr[lane + 32];
        }
        __syncthreads();
#pragma unroll 4
        for (int it = 0; it < 32; it++) {
            int c = c0 + it * 2 + chalf;
            size_t off = base + (size_t)c * TD + t0 + tl;
            float xf = resin[off];
            float xd = cbS[tl * 65 + (c - c0)];
            float qv = __fadd_rn(xf, __fsub_rn(xd, xf));   // straight-through
            float df = __fsub_rn(xf, xd);                   // commit diff
            lacc += (double)__fmul_rn(df, df);
            if (q < QL - 1) g_res[off] = __fsub_rn(xf, qv); // residual update
            float qa = (q == 0) ? qv : __fadd_rn(g_quant[off], qv);
            if (q < QL - 1) g_quant[off] = qa;
            else            out[off] = qa;                  // final quantized_out
        }
    }

    // ---- deterministic block loss partial ----
    for (int o = 16; o > 0; o >>= 1) lacc += __shfl_down_sync(0xffffffffu, lacc, o);
    if (lane == 0) sL[warp] = lacc;
    __syncthreads();
    if (tid == 0) {
        double s = 0.0;
        for (int w = 0; w < 8; w++) s += sL[w];
        g_lossPart[q * 512 + blockIdx.y * 16 + blockIdx.x] = s;
    }
}

// ---- scalars: commit loss mean + perplexity (parallel, deterministic) ----
__global__ void vq_final(float* out) {
    __shared__ double sPerp[QL], sLoss[QL];
    int warp = threadIdx.x >> 5, lane = threadIdx.x & 31;
    if (warp < QL) {
        int q = warp;
        double ls = 0.0;
        for (int b = lane; b < 512; b += 32) ls += g_lossPart[q * 512 + b];
        double ent = 0.0;
        for (int k = lane; k < KC; k += 32) {
            float cnt  = (float)g_hist[q * KC + k];
            float prob = cnt / 65536.0f;
            ent += (double)prob * log((double)prob + 1e-7);
        }
        for (int o = 16; o > 0; o >>= 1) {
            ls  += __shfl_down_sync(0xffffffffu, ls, o);
            ent += __shfl_down_sync(0xffffffffu, ent, o);
        }
        if (lane == 0) { sLoss[q] = ls / (double)ELEMS; sPerp[q] = exp(-ent); }
    }
    __syncthreads();
    if (threadIdx.x == 0) {
        double lsum = 0.0, psum = 0.0;
        for (int q = 0; q < QL; q++) { lsum += sLoss[q]; psum += sPerp[q]; }
        out[SCAL_OFF]     = (float)(lsum / (double)QL);
        out[SCAL_OFF + 1] = (float)(psum / (double)QL);
    }
}

extern "C" void kernel_launch(void* const* d_in, const int* in_sizes, int n_in,
                              void* d_out, int out_size) {
    const float* x  = (const float*)d_in[0];   // [32, 512, 2048] f32
    const float* cb = (const float*)d_in[1];   // [6, 512, 512]  f32
    float* out = (float*)d_out;

    cudaFuncSetAttribute(vq_layer,
                         cudaFuncAttributeMaxDynamicSharedMemorySize, DYN_BYTES);

    vq_prep<<<12, 256>>>(cb);
    dim3 grid(TD / TT, NB);                    // (16, 32) = 512 blocks
    for (int q = 0; q < QL; q++)
        vq_layer<<<grid, 256, DYN_BYTES>>>(x, cb, out, q);
    vq_final<<<1, QL * 32>>>(out);
}

// round 11
// speedup vs baseline: 1.1375x; 1.0340x over previous
#include <cuda_runtime.h>
#include <cuda_bf16.h>
#include <math.h>
#include <stdint.h>

// Problem shape
#define NB 32
#define CD 512
#define TD 2048
#define KC 512
#define QL 6
#define TT 128

#define ELEMS    33554432ULL
#define IDX_OFF  33554432ULL
#define SCAL_OFF 33947648ULL

// GEMM smem geometry: per stage, 4 panels of 128 rows x 32 bf16 (64B + 16B pad)
#define STRIDE   80
#define OFF_A_H  0
#define OFF_A_L  10240
#define OFF_B_H  20480
#define OFF_B_L  30720
#define STG      40960
#define DYN_BYTES (2 * STG)                   // 81920 B, 2 CTAs/SM

// Device scratch (allocation-free rule)
__device__ float         g_res  [NB * CD * TD];
__device__ float         g_quant[NB * CD * TD];
__device__ __nv_bfloat16 g_xh   [NB * TD * CD];   // residual bf16 hi, [n][t][c]
__device__ __nv_bfloat16 g_xl   [NB * TD * CD];   // residual bf16 lo
__device__ __nv_bfloat16 g_cbh  [QL * KC * CD];
__device__ __nv_bfloat16 g_cbl  [QL * KC * CD];
__device__ float         g_cbn2f[QL * KC];
__device__ unsigned int  g_hist [QL * KC];
__device__ double        g_lossPart[QL * 512];

// ---- helpers -------------------------------------------------------------
__device__ __forceinline__ void cpa16(unsigned dst, const void* src) {
    asm volatile("cp.async.cg.shared.global [%0], [%1], 16;" :: "r"(dst), "l"(src));
}
__device__ __forceinline__ void cp_commit() { asm volatile("cp.async.commit_group;"); }

// bf16 HMMA (plain sm_80+ PTX — NOT arch-"a" gated, unlike tcgen05)
__device__ __forceinline__ void mma_bf16(float* d, const uint32_t* a,
                                         uint32_t b0, uint32_t b1) {
    asm volatile(
        "mma.sync.aligned.m16n8k16.row.col.f32.bf16.bf16.f32 "
        "{%0,%1,%2,%3},{%4,%5,%6,%7},{%8,%9},{%0,%1,%2,%3};"
        : "+f"(d[0]), "+f"(d[1]), "+f"(d[2]), "+f"(d[3])
        : "r"(a[0]), "r"(a[1]), "r"(a[2]), "r"(a[3]), "r"(b0), "r"(b1));
}

__device__ __forceinline__ void merge2(float v, int k,
                                       float& D1, int& K1, float& D2, int& K2) {
    if (v < D1 || (v == D1 && k < K1)) { D2 = D1; K2 = K1; D1 = v; K1 = k; }
    else if (v < D2 || (v == D2 && k < K2)) { D2 = v; K2 = k; }
}

// ---- prep: hist zero, sequential-fp32 codebook norms, bf16 hi/lo split ----
__global__ void vq_prep(const float* cb) {
    int gid = blockIdx.x * 256 + threadIdx.x;
    if (gid < QL * KC) {
        g_hist[gid] = 0u;
        const float* row = cb + (size_t)gid * CD;
        __nv_bfloat16* ph = g_cbh + (size_t)gid * CD;
        __nv_bfloat16* pl = g_cbl + (size_t)gid * CD;
        float s = 0.0f;
        for (int c = 0; c < CD; c++) {
            float v = row[c];
            s = __fadd_rn(s, __fmul_rn(v, v));
            __nv_bfloat16 h = __float2bfloat16(v);
            ph[c] = h;
            pl[c] = __float2bfloat16(v - __bfloat162float(h));
        }
        g_cbn2f[gid] = s;
    }
}

// ---- layer-0 A split: x -> g_xh/g_xl ([n][t][c]) ----
__global__ void vq_convx(const float* x) {
    int n = blockIdx.y, t = blockIdx.x * 128 + threadIdx.x;
    const float* p = x + (size_t)n * CD * TD + t;
    size_t ao = ((size_t)n * TD + t) * CD;
    for (int g = 0; g < 64; g++) {
        unsigned hw[4], lw[4];
#pragma unroll
        for (int e2 = 0; e2 < 4; e2++) {
            float v0 = p[(size_t)(g * 8 + e2 * 2) * TD];
            float v1 = p[(size_t)(g * 8 + e2 * 2 + 1) * TD];
            __nv_bfloat16 h0 = __float2bfloat16(v0), h1 = __float2bfloat16(v1);
            __nv_bfloat16 l0 = __float2bfloat16(v0 - __bfloat162float(h0));
            __nv_bfloat16 l1 = __float2bfloat16(v1 - __bfloat162float(h1));
            hw[e2] = (unsigned)__bfloat16_as_ushort(h0) | ((unsigned)__bfloat16_as_ushort(h1) << 16);
            lw[e2] = (unsigned)__bfloat16_as_ushort(l0) | ((unsigned)__bfloat16_as_ushort(l1) << 16);
        }
        *(uint4*)(g_xh + ao + g * 8) = make_uint4(hw[0], hw[1], hw[2], hw[3]);
        *(uint4*)(g_xl + ao + g * 8) = make_uint4(lw[0], lw[1], lw[2], lw[3]);
    }
}

// ---- fused per-layer kernel ----
__global__ void __launch_bounds__(256, 2) vq_layer(
    const float* x, const float* cb, float* out, int q)
{
    extern __shared__ char dyn[];
    __shared__ float  sS1[TT];
    __shared__ int    sK[TT];
    __shared__ int    sList[TT];
    __shared__ int    sCnt;
    __shared__ double sL[8];
    __shared__ float  sRd[256];
    __shared__ int    sRk[256];

    const int tid  = threadIdx.x;
    const int lane = tid & 31;
    const int warp = tid >> 5;
    const int gid  = lane >> 2;
    const int tig  = lane & 3;
    const int tg   = warp & 3;
    const int kg   = warp >> 2;
    const int n    = blockIdx.y;
    const int t0   = blockIdx.x * TT;
    const float* resin = (q == 0) ? x : g_res;
    const float* cbq   = cb + (size_t)q * KC * CD;
    const float* cbnF  = g_cbn2f + q * KC;
    const __nv_bfloat16* cbhq = g_cbh + (size_t)q * KC * CD;
    const __nv_bfloat16* cblq = g_cbl + (size_t)q * KC * CD;
    const size_t base  = (size_t)n * CD * TD;
    const size_t abase = ((size_t)n * TD + t0) * CD;
    const unsigned sb  = (unsigned)__cvta_generic_to_shared(dyn);
    if (tid == 0) sCnt = 0;

    auto pf = [&](int s) {
        int kt = s >> 4, cc = s & 15;
        int c0 = cc * 32, k0 = kt * 128;
        unsigned so = sb + (unsigned)((s & 1) * STG);
#pragma unroll
        for (int m = 0; m < 4; m++) {
            int idx = m * 256 + tid;
            int hl  = idx >> 9;
            int row = (idx >> 2) & 127;
            int seg = idx & 3;
            cpa16(so + (hl ? OFF_A_L : OFF_A_H) + row * STRIDE + seg * 16,
                  (hl ? g_xl : g_xh) + abase + (size_t)row * CD + c0 + seg * 8);
            cpa16(so + (hl ? OFF_B_L : OFF_B_H) + row * STRIDE + seg * 16,
                  (hl ? cblq : cbhq) + (size_t)(k0 + row) * CD + c0 + seg * 8);
        }
        cp_commit();
    };

    pf(0); pf(1);

    // S1: strict sequential fp32 chain (reference rounding)
    if (tid < TT) {
        const float* p = resin + base + t0 + tid;
        float s = 0.0f;
        for (int c = 0; c < CD; c++) {
            float v = p[(size_t)c * TD];
            s = __fadd_rn(s, __fmul_rn(v, v));
        }
        sS1[tid] = s;
    }

    float bd1[4], bd2[4]; int bk1[4], bk2[4];
#pragma unroll
    for (int sl = 0; sl < 4; sl++) {
        bd1[sl] = __int_as_float(0x7f800000); bd2[sl] = bd1[sl];
        bk1[sl] = 0; bk2[sl] = 0;
    }
    float d[2][8][4];
#pragma unroll
    for (int mt = 0; mt < 2; mt++)
#pragma unroll
        for (int nt = 0; nt < 8; nt++)
#pragma unroll
            for (int r = 0; r < 4; r++) d[mt][nt][r] = 0.0f;

    // ---- HMMA mainloop: 64 steps = 4 kt x 16 c-chunks of 32 ----
    for (int s = 0; s < 64; s++) {
        asm volatile("cp.async.wait_group 1;");
        __syncthreads();
        const char* buf = dyn + (s & 1) * STG;

#pragma unroll
        for (int csi = 0; csi < 2; csi++) {
            const int cs = csi * 16;
            uint32_t ah[2][4], al[2][4];
#pragma unroll
            for (int mt = 0; mt < 2; mt++) {
                int row = tg * 32 + mt * 16 + gid;
                const char* pa = buf + OFF_A_H + row * STRIDE + (cs + tig * 2) * 2;
                ah[mt][0] = *(const uint32_t*)pa;
                ah[mt][1] = *(const uint32_t*)(pa + 8 * STRIDE);
                ah[mt][2] = *(const uint32_t*)(pa + 16);
                ah[mt][3] = *(const uint32_t*)(pa + 8 * STRIDE + 16);
                const char* pl = buf + OFF_A_L + row * STRIDE + (cs + tig * 2) * 2;
                al[mt][0] = *(const uint32_t*)pl;
                al[mt][1] = *(const uint32_t*)(pl + 8 * STRIDE);
                al[mt][2] = *(const uint32_t*)(pl + 16);
                al[mt][3] = *(const uint32_t*)(pl + 8 * STRIDE + 16);
            }
#pragma unroll
            for (int nt = 0; nt < 8; nt++) {
                int rowb = kg * 64 + nt * 8 + gid;
                const char* pb  = buf + OFF_B_H + rowb * STRIDE + (cs + tig * 2) * 2;
                const char* pbl = buf + OFF_B_L + rowb * STRIDE + (cs + tig * 2) * 2;
                uint32_t bh0 = *(const uint32_t*)pb;
                uint32_t bh1 = *(const uint32_t*)(pb + 16);
                uint32_t bl0 = *(const uint32_t*)pbl;
                uint32_t bl1 = *(const uint32_t*)(pbl + 16);
#pragma unroll
                for (int mt = 0; mt < 2; mt++) {
                    mma_bf16(d[mt][nt], ah[mt], bh0, bh1);
                    mma_bf16(d[mt][nt], ah[mt], bl0, bl1);
                    mma_bf16(d[mt][nt], al[mt], bh0, bh1);
                    mma_bf16(d[mt][nt], al[mt], bl0, bl1);
                }
            }
        }
        __syncthreads();
        if (s + 2 < 64) pf(s + 2); else cp_commit();

        if ((s & 15) == 15) {
            int kt = s >> 4;
#pragma unroll
            for (int mt = 0; mt < 2; mt++)
#pragma unroll
                for (int h = 0; h < 2; h++) {
                    int slot = mt * 2 + h;
                    int tok  = tg * 32 + mt * 16 + h * 8 + gid;
                    float s1v = sS1[tok];
#pragma unroll
                    for (int nt = 0; nt < 8; nt++)
#pragma unroll
                        for (int e = 0; e < 2; e++) {
                            int k = kt * 128 + kg * 64 + nt * 8 + tig * 2 + e;
                            float da = __fmaf_rn(-2.0f, d[mt][nt][h * 2 + e], cbnF[k]) + s1v;
                            merge2(da, k, bd1[slot], bk1[slot], bd2[slot], bk2[slot]);
                            d[mt][nt][h * 2 + e] = 0.0f;
                        }
                }
        }
    }
    asm volatile("cp.async.wait_group 0;");
    __syncthreads();

    // ---- cross-thread top-2 reduce ----
    float* eD1 = (float*)dyn;
    float* eD2 = (float*)(dyn + 4096);
    int*   eK1 = (int*)(dyn + 8192);
    int*   eK2 = (int*)(dyn + 12288);
    {
        int g = tig * 2 + kg;
#pragma unroll
        for (int mt = 0; mt < 2; mt++)
#pragma unroll
            for (int h = 0; h < 2; h++) {
                int slot = mt * 2 + h;
                int tok  = tg * 32 + mt * 16 + h * 8 + gid;
                eD1[g * TT + tok] = bd1[slot]; eK1[g * TT + tok] = bk1[slot];
                eD2[g * TT + tok] = bd2[slot]; eK2[g * TT + tok] = bk2[slot];
            }
    }
    __syncthreads();
    if (tid < TT) {
        float D1 = __int_as_float(0x7f800000), D2 = D1;
        int K1 = 0, K2 = 0;
#pragma unroll
        for (int g = 0; g < 8; g++) {
            merge2(eD1[g * TT + tid], eK1[g * TT + tid], D1, K1, D2, K2);
            merge2(eD2[g * TT + tid], eK2[g * TT + tid], D1, K1, D2, K2);
        }
        sK[tid] = K1;
        float tau = 2e-6f * (sS1[tid] + 512.0f) + 4e-5f;
        if (D2 - D1 < tau) {
            int slot = atomicAdd(&sCnt, 1);
            sList[slot] = tid;
        }
    }
    __syncthreads();

    // ---- exact rescan of flagged tokens (reference fp32 chain) ----
    {
        int cnt = sCnt;
        for (int e = 0; e < cnt; e++) {
            int tl = sList[e];
            const float* xp = resin + base + t0 + tl;
            const float* cA = cbq + (size_t)tid * CD;
            const float* cB = cbq + (size_t)(tid + 256) * CD;
            float a0 = 0.0f, a1 = 0.0f;
            for (int c = 0; c < CD; c++) {
                float xv = xp[(size_t)c * TD];
                a0 = __fmaf_rn(cA[c], xv, a0);
                a1 = __fmaf_rn(cB[c], xv, a1);
            }
            float S = sS1[tl];
            float d0 = __fadd_rn(__fsub_rn(S, __fmul_rn(2.0f, a0)), cbnF[tid]);
            float d1 = __fadd_rn(__fsub_rn(S, __fmul_rn(2.0f, a1)), cbnF[tid + 256]);
            float bdv = d0; int bkv = tid;
            if (d1 < bdv) { bdv = d1; bkv = tid + 256; }
            sRd[tid] = bdv; sRk[tid] = bkv;
            __syncthreads();
            for (int off = 128; off > 0; off >>= 1) {
                if (tid < off) {
                    float od = sRd[tid + off]; int ok = sRk[tid + off];
                    if (od < sRd[tid] || (od == sRd[tid] && ok < sRk[tid])) {
                        sRd[tid] = od; sRk[tid] = ok;
                    }
                }
                __syncthreads();
            }
            if (tid == 0) sK[tl] = sRk[0];
            __syncthreads();
        }
    }

    // ---- indices + histogram ----
    if (tid < TT) {
        int K = sK[tid];
        out[IDX_OFF + ((size_t)(n * TD + t0 + tid)) * QL + q] = (float)K;
        atomicAdd(&g_hist[q * KC + K], 1u);
    }

    // ---- gather + update (reference fp32 chain) + next-layer bf16 split ----
    float* cbS = (float*)dyn;                  // [128][65]
    const int tl   = tid & 127;
    const int half = tid >> 7;
    double lacc = 0.0;
    for (int ch = 0; ch < 8; ch++) {
        const int c0 = ch * 64;
        __syncthreads();
        for (int u = 0; u < 16; u++) {
            int tt = warp * 16 + u;
            const float* cr = cbq + (size_t)sK[tt] * CD + c0;
            cbS[tt * 65 + lane]      = cr[lane];
            cbS[tt * 65 + lane + 32] = cr[lane + 32];
        }
        __syncthreads();
#pragma unroll
        for (int gph = 0; gph < 4; gph++) {
            unsigned hw[4] = {0, 0, 0, 0}, lw[4] = {0, 0, 0, 0};
            int cb0 = c0 + half * 32 + gph * 8;
#pragma unroll
            for (int e = 0; e < 8; e++) {
                int c = cb0 + e;
                size_t off = base + (size_t)c * TD + t0 + tl;
                float xf = resin[off];
                float xd = cbS[tl * 65 + (c - c0)];
                float qv = __fadd_rn(xf, __fsub_rn(xd, xf));
                float df = __fsub_rn(xf, xd);
                lacc += (double)__fmul_rn(df, df);
                float qa = (q == 0) ? qv : __fadd_rn(g_quant[off], qv);
                if (q < QL - 1) {
                    float rn = __fsub_rn(xf, qv);
                    g_res[off]   = rn;
                    g_quant[off] = qa;
                    __nv_bfloat16 h = __float2bfloat16(rn);
                    __nv_bfloat16 l = __float2bfloat16(rn - __bfloat162float(h));
                    hw[e >> 1] |= (unsigned)__bfloat16_as_ushort(h) << ((e & 1) * 16);
                    lw[e >> 1] |= (unsigned)__bfloat16_as_ushort(l) << ((e & 1) * 16);
                } else {
                    out[off] = qa;
                }
            }
            if (q < QL - 1) {
                size_t ao = abase + (size_t)tl * CD + cb0;
                *(uint4*)(g_xh + ao) = make_uint4(hw[0], hw[1], hw[2], hw[3]);
                *(uint4*)(g_xl + ao) = make_uint4(lw[0], lw[1], lw[2], lw[3]);
            }
        }
    }

    // ---- deterministic block loss partial ----
    for (int o = 16; o > 0; o >>= 1) lacc += __shfl_down_sync(0xffffffffu, lacc, o);
    if (lane == 0) sL[warp] = lacc;
    __syncthreads();
    if (tid == 0) {
        double s = 0.0;
        for (int w = 0; w < 8; w++) s += sL[w];
        g_lossPart[q * 512 + blockIdx.y * 16 + blockIdx.x] = s;
    }
}

// ---- scalars: commit loss mean + perplexity ----
__global__ void vq_final(float* out) {
    __shared__ double sPerp[QL], sLoss[QL];
    int warp = threadIdx.x >> 5, lane = threadIdx.x & 31;
    if (warp < QL) {
        int q = warp;
        double ls = 0.0;
        for (int b = lane; b < 512; b += 32) ls += g_lossPart[q * 512 + b];
        double ent = 0.0;
        for (int k = lane; k < KC; k += 32) {
            float cnt  = (float)g_hist[q * KC + k];
            float prob = cnt / 65536.0f;
            ent += (double)prob * log((double)prob + 1e-7);
        }
        for (int o = 16; o > 0; o >>= 1) {
            ls  += __shfl_down_sync(0xffffffffu, ls, o);
            ent += __shfl_down_sync(0xffffffffu, ent, o);
        }
        if (lane == 0) { sLoss[q] = ls / (double)ELEMS; sPerp[q] = exp(-ent); }
    }
    __syncthreads();
    if (threadIdx.x == 0) {
        double lsum = 0.0, psum = 0.0;
        for (int q = 0; q < QL; q++) { lsum += sLoss[q]; psum += sPerp[q]; }
        out[SCAL_OFF]     = (float)(lsum / (double)QL);
        out[SCAL_OFF + 1] = (float)(psum / (double)QL);
    }
}

extern "C" void kernel_launch(void* const* d_in, const int* in_sizes, int n_in,
                              void* d_out, int out_size) {
    const float* x  = (const float*)d_in[0];   // [32, 512, 2048] f32
    const float* cb = (const float*)d_in[1];   // [6, 512, 512]  f32
    float* out = (float*)d_out;

    cudaFuncSetAttribute(vq_layer,
                         cudaFuncAttributeMaxDynamicSharedMemorySize, DYN_BYTES);

    vq_prep<<<12, 256>>>(cb);
    vq_convx<<<dim3(16, 32), 128>>>(x);
    dim3 grid(TD / TT, NB);                    // (16, 32) = 512 blocks
    for (int q = 0; q < QL; q++)
        vq_layer<<<grid, 256, DYN_BYTES>>>(x, cb, out, q);
    vq_final<<<1, QL * 32>>>(out);
}

// round 12
// speedup vs baseline: 1.1802x; 1.0376x over previous
#include <cuda_runtime.h>
#include <cuda_bf16.h>
#include <math.h>
#include <stdint.h>

// Problem shape
#define NB 32
#define CD 512
#define TD 2048
#define KC 512
#define QL 6
#define TT 128

#define ELEMS    33554432ULL
#define IDX_OFF  33554432ULL
#define SCAL_OFF 33947648ULL

// GEMM smem geometry: per stage, 4 panels of 128 rows x 32 bf16 (64B + 16B pad)
#define STRIDE   80
#define OFF_A_H  0
#define OFF_A_L  10240
#define OFF_B_H  20480
#define OFF_B_L  30720
#define STG      40960
#define DYN_BYTES (2 * STG)                   // 81920 B, 2 CTAs/SM

// Device scratch (allocation-free rule)
__device__ float         g_res  [NB * CD * TD];
__device__ float         g_quant[NB * CD * TD];
__device__ __nv_bfloat16 g_xh   [NB * TD * CD];   // residual bf16 hi, [n][t][c]
__device__ __nv_bfloat16 g_xl   [NB * TD * CD];   // residual bf16 lo
__device__ __nv_bfloat16 g_cbh  [QL * KC * CD];
__device__ __nv_bfloat16 g_cbl  [QL * KC * CD];
__device__ float         g_cbn2f[QL * KC];
__device__ unsigned int  g_hist [QL * KC];
__device__ double        g_lossPart[QL * 512];

// ---- helpers -------------------------------------------------------------
__device__ __forceinline__ void cpa16(unsigned dst, const void* src) {
    asm volatile("cp.async.cg.shared.global [%0], [%1], 16;" :: "r"(dst), "l"(src));
}
__device__ __forceinline__ void cp_commit() { asm volatile("cp.async.commit_group;"); }

// bf16 HMMA m16n8k16 (plain sm_80+ PTX — NOT arch-"a" gated, unlike tcgen05)
__device__ __forceinline__ void mma_bf16(float* d, const uint32_t* a,
                                         uint32_t b0, uint32_t b1) {
    asm volatile(
        "mma.sync.aligned.m16n8k16.row.col.f32.bf16.bf16.f32 "
        "{%0,%1,%2,%3},{%4,%5,%6,%7},{%8,%9},{%0,%1,%2,%3};"
        : "+f"(d[0]), "+f"(d[1]), "+f"(d[2]), "+f"(d[3])
        : "r"(a[0]), "r"(a[1]), "r"(a[2]), "r"(a[3]), "r"(b0), "r"(b1));
}

// ldmatrix x4 (sm_75+): four 8x8 b16 tiles, lane i supplies row addr for tile i>>3
__device__ __forceinline__ void ldsm4(uint32_t* r, unsigned a) {
    asm volatile("ldmatrix.sync.aligned.m8n8.x4.shared.b16 {%0,%1,%2,%3}, [%4];"
                 : "=r"(r[0]), "=r"(r[1]), "=r"(r[2]), "=r"(r[3]) : "r"(a));
}

__device__ __forceinline__ void merge2(float v, int k,
                                       float& D1, int& K1, float& D2, int& K2) {
    if (v < D1 || (v == D1 && k < K1)) { D2 = D1; K2 = K1; D1 = v; K1 = k; }
    else if (v < D2 || (v == D2 && k < K2)) { D2 = v; K2 = k; }
}

// ---- prep: hist zero, sequential-fp32 codebook norms, bf16 hi/lo split ----
__global__ void vq_prep(const float* cb) {
    int gid = blockIdx.x * 256 + threadIdx.x;
    if (gid < QL * KC) {
        g_hist[gid] = 0u;
        const float* row = cb + (size_t)gid * CD;
        __nv_bfloat16* ph = g_cbh + (size_t)gid * CD;
        __nv_bfloat16* pl = g_cbl + (size_t)gid * CD;
        float s = 0.0f;
        for (int c = 0; c < CD; c++) {
            float v = row[c];
            s = __fadd_rn(s, __fmul_rn(v, v));
            __nv_bfloat16 h = __float2bfloat16(v);
            ph[c] = h;
            pl[c] = __float2bfloat16(v - __bfloat162float(h));
        }
        g_cbn2f[gid] = s;
    }
}

// ---- layer-0 A split: x -> g_xh/g_xl ([n][t][c]) ----
__global__ void vq_convx(const float* x) {
    int n = blockIdx.y, t = blockIdx.x * 128 + threadIdx.x;
    const float* p = x + (size_t)n * CD * TD + t;
    size_t ao = ((size_t)n * TD + t) * CD;
    for (int g = 0; g < 64; g++) {
        unsigned hw[4], lw[4];
#pragma unroll
        for (int e2 = 0; e2 < 4; e2++) {
            float v0 = p[(size_t)(g * 8 + e2 * 2) * TD];
            float v1 = p[(size_t)(g * 8 + e2 * 2 + 1) * TD];
            __nv_bfloat16 h0 = __float2bfloat16(v0), h1 = __float2bfloat16(v1);
            __nv_bfloat16 l0 = __float2bfloat16(v0 - __bfloat162float(h0));
            __nv_bfloat16 l1 = __float2bfloat16(v1 - __bfloat162float(h1));
            hw[e2] = (unsigned)__bfloat16_as_ushort(h0) | ((unsigned)__bfloat16_as_ushort(h1) << 16);
            lw[e2] = (unsigned)__bfloat16_as_ushort(l0) | ((unsigned)__bfloat16_as_ushort(l1) << 16);
        }
        *(uint4*)(g_xh + ao + g * 8) = make_uint4(hw[0], hw[1], hw[2], hw[3]);
        *(uint4*)(g_xl + ao + g * 8) = make_uint4(lw[0], lw[1], lw[2], lw[3]);
    }
}

// ---- fused per-layer kernel ----
__global__ void __launch_bounds__(256, 2) vq_layer(
    const float* x, const float* cb, float* out, int q)
{
    extern __shared__ char dyn[];
    __shared__ float  sS1[TT];
    __shared__ int    sK[TT];
    __shared__ int    sList[TT];
    __shared__ int    sCnt;
    __shared__ double sL[8];
    __shared__ float  sRd[256];
    __shared__ int    sRk[256];

    const int tid  = threadIdx.x;
    const int lane = tid & 31;
    const int warp = tid >> 5;
    const int gid  = lane >> 2;
    const int tig  = lane & 3;
    const int tg   = warp & 3;
    const int kg   = warp >> 2;
    const int n    = blockIdx.y;
    const int t0   = blockIdx.x * TT;
    const float* resin = (q == 0) ? x : g_res;
    const float* cbq   = cb + (size_t)q * KC * CD;
    const float* cbnF  = g_cbn2f + q * KC;
    const __nv_bfloat16* cbhq = g_cbh + (size_t)q * KC * CD;
    const __nv_bfloat16* cblq = g_cbl + (size_t)q * KC * CD;
    const size_t base  = (size_t)n * CD * TD;
    const size_t abase = ((size_t)n * TD + t0) * CD;
    const unsigned sb  = (unsigned)__cvta_generic_to_shared(dyn);
    if (tid == 0) sCnt = 0;

    auto pf = [&](int s) {
        int kt = s >> 4, cc = s & 15;
        int c0 = cc * 32, k0 = kt * 128;
        unsigned so = sb + (unsigned)((s & 1) * STG);
#pragma unroll
        for (int m = 0; m < 4; m++) {
            int idx = m * 256 + tid;
            int hl  = idx >> 9;
            int row = (idx >> 2) & 127;
            int seg = idx & 3;
            cpa16(so + (hl ? OFF_A_L : OFF_A_H) + row * STRIDE + seg * 16,
                  (hl ? g_xl : g_xh) + abase + (size_t)row * CD + c0 + seg * 8);
            cpa16(so + (hl ? OFF_B_L : OFF_B_H) + row * STRIDE + seg * 16,
                  (hl ? cblq : cbhq) + (size_t)(k0 + row) * CD + c0 + seg * 8);
        }
        cp_commit();
    };

    pf(0); pf(1);

    // S1: strict sequential fp32 chain (reference rounding)
    if (tid < TT) {
        const float* p = resin + base + t0 + tid;
        float s = 0.0f;
        for (int c = 0; c < CD; c++) {
            float v = p[(size_t)c * TD];
            s = __fadd_rn(s, __fmul_rn(v, v));
        }
        sS1[tid] = s;
    }

    float bd1[4], bd2[4]; int bk1[4], bk2[4];
#pragma unroll
    for (int sl = 0; sl < 4; sl++) {
        bd1[sl] = __int_as_float(0x7f800000); bd2[sl] = bd1[sl];
        bk1[sl] = 0; bk2[sl] = 0;
    }
    float d[2][8][4];
#pragma unroll
    for (int mt = 0; mt < 2; mt++)
#pragma unroll
        for (int nt = 0; nt < 8; nt++)
#pragma unroll
            for (int r = 0; r < 4; r++) d[mt][nt][r] = 0.0f;

    // ldmatrix lane-address components (precomputed)
    const unsigned aRow  = (unsigned)(lane & 15);          // A: row within 16
    const unsigned aColB = (unsigned)((lane >> 4) * 16);   // A: +8 cols (16B)
    const unsigned bNtl  = (unsigned)((lane >> 4) & 1);    // B: which nt of pair
    const unsigned bRow  = (unsigned)(lane & 7);
    const unsigned bColB = (unsigned)(((lane >> 3) & 1) * 16);

    // ---- HMMA mainloop: 64 steps = 4 kt x 16 c-chunks of 32 ----
    for (int s = 0; s < 64; s++) {
        asm volatile("cp.async.wait_group 1;");
        __syncthreads();
        const unsigned bufo = sb + (unsigned)((s & 1) * STG);

#pragma unroll
        for (int csi = 0; csi < 2; csi++) {
            const unsigned csB = (unsigned)(csi * 32);     // 16 cols * 2B

            // A fragments via ldmatrix x4 (hi + lo, 2 mt)
            uint32_t ah[2][4], al[2][4];
#pragma unroll
            for (int mt = 0; mt < 2; mt++) {
                unsigned ra = bufo + OFF_A_H
                            + (unsigned)((tg * 32 + mt * 16) + aRow) * STRIDE
                            + csB + aColB;
                ldsm4(ah[mt], ra);
                ldsm4(al[mt], ra + (OFF_A_L - OFF_A_H));
            }
            // B fragments via ldmatrix x4: each loads an nt pair (hi + lo)
            uint32_t bh[8][2], bl[8][2];
#pragma unroll
            for (int j = 0; j < 4; j++) {
                unsigned ntl = (unsigned)(2 * j) + bNtl;
                unsigned rb  = bufo + OFF_B_H
                             + (unsigned)(kg * 64 + ntl * 8 + bRow) * STRIDE
                             + csB + bColB;
                uint32_t r4[4];
                ldsm4(r4, rb);
                bh[2*j][0] = r4[0]; bh[2*j][1] = r4[1];
                bh[2*j+1][0] = r4[2]; bh[2*j+1][1] = r4[3];
                ldsm4(r4, rb + (OFF_B_L - OFF_B_H));
                bl[2*j][0] = r4[0]; bl[2*j][1] = r4[1];
                bl[2*j+1][0] = r4[2]; bl[2*j+1][1] = r4[3];
            }
#pragma unroll
            for (int nt = 0; nt < 8; nt++)
#pragma unroll
                for (int mt = 0; mt < 2; mt++) {
                    mma_bf16(d[mt][nt], ah[mt], bh[nt][0], bh[nt][1]);  // hh
                    mma_bf16(d[mt][nt], ah[mt], bl[nt][0], bl[nt][1]);  // hl
                    mma_bf16(d[mt][nt], al[mt], bh[nt][0], bh[nt][1]);  // lh
                    // ll dropped: |sum al*bl| ~2e-5 << tau, rescue net covers it
                }
        }
        __syncthreads();
        if (s + 2 < 64) pf(s + 2); else cp_commit();

        if ((s & 15) == 15) {
            int kt = s >> 4;
#pragma unroll
            for (int mt = 0; mt < 2; mt++)
#pragma unroll
                for (int h = 0; h < 2; h++) {
                    int slot = mt * 2 + h;
                    int tok  = tg * 32 + mt * 16 + h * 8 + gid;
                    float s1v = sS1[tok];
#pragma unroll
                    for (int nt = 0; nt < 8; nt++)
#pragma unroll
                        for (int e = 0; e < 2; e++) {
                            int k = kt * 128 + kg * 64 + nt * 8 + tig * 2 + e;
                            float da = __fmaf_rn(-2.0f, d[mt][nt][h * 2 + e], cbnF[k]) + s1v;
                            merge2(da, k, bd1[slot], bk1[slot], bd2[slot], bk2[slot]);
                            d[mt][nt][h * 2 + e] = 0.0f;
                        }
                }
        }
    }
    asm volatile("cp.async.wait_group 0;");
    __syncthreads();

    // ---- cross-thread top-2 reduce ----
    float* eD1 = (float*)dyn;
    float* eD2 = (float*)(dyn + 4096);
    int*   eK1 = (int*)(dyn + 8192);
    int*   eK2 = (int*)(dyn + 12288);
    {
        int g = tig * 2 + kg;
#pragma unroll
        for (int mt = 0; mt < 2; mt++)
#pragma unroll
            for (int h = 0; h < 2; h++) {
                int slot = mt * 2 + h;
                int tok  = tg * 32 + mt * 16 + h * 8 + gid;
                eD1[g * TT + tok] = bd1[slot]; eK1[g * TT + tok] = bk1[slot];
                eD2[g * TT + tok] = bd2[slot]; eK2[g * TT + tok] = bk2[slot];
            }
    }
    __syncthreads();
    if (tid < TT) {
        float D1 = __int_as_float(0x7f800000), D2 = D1;
        int K1 = 0, K2 = 0;
#pragma unroll
        for (int g = 0; g < 8; g++) {
            merge2(eD1[g * TT + tid], eK1[g * TT + tid], D1, K1, D2, K2);
            merge2(eD2[g * TT + tid], eK2[g * TT + tid], D1, K1, D2, K2);
        }
        sK[tid] = K1;
        float tau = 2e-6f * (sS1[tid] + 512.0f) + 4e-5f;
        if (D2 - D1 < tau) {
            int slot = atomicAdd(&sCnt, 1);
            sList[slot] = tid;
        }
    }
    __syncthreads();

    // ---- exact rescan of flagged tokens (reference fp32 chain) ----
    {
        int cnt = sCnt;
        for (int e = 0; e < cnt; e++) {
            int tl = sList[e];
            const float* xp = resin + base + t0 + tl;
            const float* cA = cbq + (size_t)tid * CD;
            const float* cB = cbq + (size_t)(tid + 256) * CD;
            float a0 = 0.0f, a1 = 0.0f;
            for (int c = 0; c < CD; c++) {
                float xv = xp[(size_t)c * TD];
                a0 = __fmaf_rn(cA[c], xv, a0);
                a1 = __fmaf_rn(cB[c], xv, a1);
            }
            float S = sS1[tl];
            float d0 = __fadd_rn(__fsub_rn(S, __fmul_rn(2.0f, a0)), cbnF[tid]);
            float d1 = __fadd_rn(__fsub_rn(S, __fmul_rn(2.0f, a1)), cbnF[tid + 256]);
            float bdv = d0; int bkv = tid;
            if (d1 < bdv) { bdv = d1; bkv = tid + 256; }
            sRd[tid] = bdv; sRk[tid] = bkv;
            __syncthreads();
            for (int off = 128; off > 0; off >>= 1) {
                if (tid < off) {
                    float od = sRd[tid + off]; int ok = sRk[tid + off];
                    if (od < sRd[tid] || (od == sRd[tid] && ok < sRk[tid])) {
                        sRd[tid] = od; sRk[tid] = ok;
                    }
                }
                __syncthreads();
            }
            if (tid == 0) sK[tl] = sRk[0];
            __syncthreads();
        }
    }

    // ---- indices + histogram ----
    if (tid < TT) {
        int K = sK[tid];
        out[IDX_OFF + ((size_t)(n * TD + t0 + tid)) * QL + q] = (float)K;
        atomicAdd(&g_hist[q * KC + K], 1u);
    }

    // ---- gather + update (reference fp32 chain) + next-layer bf16 split ----
    float* cbS = (float*)dyn;                  // [128][65]
    const int tl   = tid & 127;
    const int half = tid >> 7;
    double lacc = 0.0;
    for (int ch = 0; ch < 8; ch++) {
        const int c0 = ch * 64;
        __syncthreads();
        for (int u = 0; u < 16; u++) {
            int tt = warp * 16 + u;
            const float* cr = cbq + (size_t)sK[tt] * CD + c0;
            cbS[tt * 65 + lane]      = cr[lane];
            cbS[tt * 65 + lane + 32] = cr[lane + 32];
        }
        __syncthreads();
#pragma unroll
        for (int gph = 0; gph < 4; gph++) {
            unsigned hw[4] = {0, 0, 0, 0}, lw[4] = {0, 0, 0, 0};
            int cb0 = c0 + half * 32 + gph * 8;
#pragma unroll
            for (int e = 0; e < 8; e++) {
                int c = cb0 + e;
                size_t off = base + (size_t)c * TD + t0 + tl;
                float xf = resin[off];
                float xd = cbS[tl * 65 + (c - c0)];
                float qv = __fadd_rn(xf, __fsub_rn(xd, xf));
                float df = __fsub_rn(xf, xd);
                lacc += (double)__fmul_rn(df, df);
                float qa = (q == 0) ? qv : __fadd_rn(g_quant[off], qv);
                if (q < QL - 1) {
                    float rn = __fsub_rn(xf, qv);
                    g_res[off]   = rn;
                    g_quant[off] = qa;
                    __nv_bfloat16 h = __float2bfloat16(rn);
                    __nv_bfloat16 l = __float2bfloat16(rn - __bfloat162float(h));
                    hw[e >> 1] |= (unsigned)__bfloat16_as_ushort(h) << ((e & 1) * 16);
                    lw[e >> 1] |= (unsigned)__bfloat16_as_ushort(l) << ((e & 1) * 16);
                } else {
                    out[off] = qa;
                }
            }
            if (q < QL - 1) {
                size_t ao = abase + (size_t)tl * CD + cb0;
                *(uint4*)(g_xh + ao) = make_uint4(hw[0], hw[1], hw[2], hw[3]);
                *(uint4*)(g_xl + ao) = make_uint4(lw[0], lw[1], lw[2], lw[3]);
            }
        }
    }

    // ---- deterministic block loss partial ----
    for (int o = 16; o > 0; o >>= 1) lacc += __shfl_down_sync(0xffffffffu, lacc, o);
    if (lane == 0) sL[warp] = lacc;
    __syncthreads();
    if (tid == 0) {
        double s = 0.0;
        for (int w = 0; w < 8; w++) s += sL[w];
        g_lossPart[q * 512 + blockIdx.y * 16 + blockIdx.x] = s;
    }
}

// ---- scalars: commit loss mean + perplexity ----
__global__ void vq_final(float* out) {
    __shared__ double sPerp[QL], sLoss[QL];
    int warp = threadIdx.x >> 5, lane = threadIdx.x & 31;
    if (warp < QL) {
        int q = warp;
        double ls = 0.0;
        for (int b = lane; b < 512; b += 32) ls += g_lossPart[q * 512 + b];
        double ent = 0.0;
        for (int k = lane; k < KC; k += 32) {
            float cnt  = (float)g_hist[q * KC + k];
            float prob = cnt / 65536.0f;
            ent += (double)prob * log((double)prob + 1e-7);
        }
        for (int o = 16; o > 0; o >>= 1) {
            ls  += __shfl_down_sync(0xffffffffu, ls, o);
            ent += __shfl_down_sync(0xffffffffu, ent, o);
        }
        if (lane == 0) { sLoss[q] = ls / (double)ELEMS; sPerp[q] = exp(-ent); }
    }
    __syncthreads();
    if (threadIdx.x == 0) {
        double lsum = 0.0, psum = 0.0;
        for (int q = 0; q < QL; q++) { lsum += sLoss[q]; psum += sPerp[q]; }
        out[SCAL_OFF]     = (float)(lsum / (double)QL);
        out[SCAL_OFF + 1] = (float)(psum / (double)QL);
    }
}

extern "C" void kernel_launch(void* const* d_in, const int* in_sizes, int n_in,
                              void* d_out, int out_size) {
    const float* x  = (const float*)d_in[0];   // [32, 512, 2048] f32
    const float* cb = (const float*)d_in[1];   // [6, 512, 512]  f32
    float* out = (float*)d_out;

    cudaFuncSetAttribute(vq_layer,
                         cudaFuncAttributeMaxDynamicSharedMemorySize, DYN_BYTES);

    vq_prep<<<12, 256>>>(cb);
    vq_convx<<<dim3(16, 32), 128>>>(x);
    dim3 grid(TD / TT, NB);                    // (16, 32) = 512 blocks
    for (int q = 0; q < QL; q++)
        vq_layer<<<grid, 256, DYN_BYTES>>>(x, cb, out, q);
    vq_final<<<1, QL * 32>>>(out);
}

// round 14
// speedup vs baseline: 1.3159x; 1.1150x over previous
#include <cuda_runtime.h>
#include <cuda_bf16.h>
#include <math.h>
#include <stdint.h>

// Problem shape
#define NB 32
#define CD 512
#define TD 2048
#define KC 512
#define QL 6
#define TT 128

#define ELEMS    33554432ULL
#define IDX_OFF  33554432ULL
#define SCAL_OFF 33947648ULL

// GEMM smem geometry: per stage, 4 panels of 128 rows x 32 bf16 (64B + 16B pad)
#define STRIDE   80
#define OFF_A_H  0
#define OFF_A_L  10240
#define OFF_B_H  20480
#define OFF_B_L  30720
#define STG      40960
#define DYN_BYTES (2 * STG)                   // 81920 B, 2 CTAs/SM

// Device scratch (allocation-free rule)
__device__ float         g_res  [NB * CD * TD];
__device__ float         g_quant[NB * CD * TD];
__device__ __nv_bfloat16 g_xh   [NB * TD * CD];   // residual bf16 hi, [n][t][c]
__device__ __nv_bfloat16 g_xl   [NB * TD * CD];   // residual bf16 lo
__device__ __nv_bfloat16 g_cbh  [QL * KC * CD];
__device__ __nv_bfloat16 g_cbl  [QL * KC * CD];
__device__ float         g_cbT  [QL * CD * KC];   // fp32 codebook transposed [q][c][k]
__device__ float         g_cbn2f[QL * KC];
__device__ unsigned int  g_hist [QL * KC];
__device__ double        g_lossPart[QL * 512];

// ---- helpers -------------------------------------------------------------
__device__ __forceinline__ void cpa16(unsigned dst, const void* src) {
    asm volatile("cp.async.cg.shared.global [%0], [%1], 16;" :: "r"(dst), "l"(src));
}
__device__ __forceinline__ void cp_commit() { asm volatile("cp.async.commit_group;"); }

// bf16 HMMA m16n8k16 (plain sm_80+ PTX — NOT arch-"a" gated, unlike tcgen05)
__device__ __forceinline__ void mma_bf16(float* d, const uint32_t* a,
                                         uint32_t b0, uint32_t b1) {
    asm volatile(
        "mma.sync.aligned.m16n8k16.row.col.f32.bf16.bf16.f32 "
        "{%0,%1,%2,%3},{%4,%5,%6,%7},{%8,%9},{%0,%1,%2,%3};"
        : "+f"(d[0]), "+f"(d[1]), "+f"(d[2]), "+f"(d[3])
        : "r"(a[0]), "r"(a[1]), "r"(a[2]), "r"(a[3]), "r"(b0), "r"(b1));
}

// ldmatrix x4 (sm_75+)
__device__ __forceinline__ void ldsm4(uint32_t* r, unsigned a) {
    asm volatile("ldmatrix.sync.aligned.m8n8.x4.shared.b16 {%0,%1,%2,%3}, [%4];"
                 : "=r"(r[0]), "=r"(r[1]), "=r"(r[2]), "=r"(r[3]) : "r"(a));
}

__device__ __forceinline__ void merge2(float v, int k,
                                       float& D1, int& K1, float& D2, int& K2) {
    if (v < D1 || (v == D1 && k < K1)) { D2 = D1; K2 = K1; D1 = v; K1 = k; }
    else if (v < D2 || (v == D2 && k < K2)) { D2 = v; K2 = k; }
}

// ---- prep: hist zero, sequential-fp32 codebook norms, bf16 hi/lo split ----
__global__ void vq_prep(const float* cb) {
    int gid = blockIdx.x * 256 + threadIdx.x;
    if (gid < QL * KC) {
        g_hist[gid] = 0u;
        const float* row = cb + (size_t)gid * CD;
        __nv_bfloat16* ph = g_cbh + (size_t)gid * CD;
        __nv_bfloat16* pl = g_cbl + (size_t)gid * CD;
        float s = 0.0f;
        for (int c = 0; c < CD; c++) {
            float v = row[c];
            s = __fadd_rn(s, __fmul_rn(v, v));
            __nv_bfloat16 h = __float2bfloat16(v);
            ph[c] = h;
            pl[c] = __float2bfloat16(v - __bfloat162float(h));
        }
        g_cbn2f[gid] = s;
    }
}

// ---- coalesced codebook transpose: g_cbT[q][c][k] = cb[q][k][c] ----
__global__ void vq_tr(const float* cb) {
    __shared__ float tile[32][33];
    int q  = blockIdx.z;
    int k0 = blockIdx.x * 32, c0 = blockIdx.y * 32;
    const float* src = cb + (size_t)q * KC * CD;
    for (int i = threadIdx.y; i < 32; i += 8)
        tile[i][threadIdx.x] = src[(size_t)(k0 + i) * CD + c0 + threadIdx.x];
    __syncthreads();
    float* dst = g_cbT + (size_t)q * CD * KC;
    for (int i = threadIdx.y; i < 32; i += 8)
        dst[(size_t)(c0 + i) * KC + k0 + threadIdx.x] = tile[threadIdx.x][i];
}

// ---- layer-0 A split: x -> g_xh/g_xl ([n][t][c]) ----
__global__ void vq_convx(const float* x) {
    int n = blockIdx.y, t = blockIdx.x * 128 + threadIdx.x;
    const float* p = x + (size_t)n * CD * TD + t;
    size_t ao = ((size_t)n * TD + t) * CD;
    for (int g = 0; g < 64; g++) {
        unsigned hw[4], lw[4];
#pragma unroll
        for (int e2 = 0; e2 < 4; e2++) {
            float v0 = p[(size_t)(g * 8 + e2 * 2) * TD];
            float v1 = p[(size_t)(g * 8 + e2 * 2 + 1) * TD];
            __nv_bfloat16 h0 = __float2bfloat16(v0), h1 = __float2bfloat16(v1);
            __nv_bfloat16 l0 = __float2bfloat16(v0 - __bfloat162float(h0));
            __nv_bfloat16 l1 = __float2bfloat16(v1 - __bfloat162float(h1));
            hw[e2] = (unsigned)__bfloat16_as_ushort(h0) | ((unsigned)__bfloat16_as_ushort(h1) << 16);
            lw[e2] = (unsigned)__bfloat16_as_ushort(l0) | ((unsigned)__bfloat16_as_ushort(l1) << 16);
        }
        *(uint4*)(g_xh + ao + g * 8) = make_uint4(hw[0], hw[1], hw[2], hw[3]);
        *(uint4*)(g_xl + ao + g * 8) = make_uint4(lw[0], lw[1], lw[2], lw[3]);
    }
}

// ---- fused per-layer kernel ----
__global__ void __launch_bounds__(256, 2) vq_layer(
    const float* x, const float* cb, float* out, int q)
{
    extern __shared__ char dyn[];
    __shared__ float  sS1[TT];
    __shared__ int    sK[TT];
    __shared__ int    sList[TT];
    __shared__ int    sCnt;
    __shared__ double sL[8];
    __shared__ float  sRd[256];
    __shared__ int    sRk[256];

    const int tid  = threadIdx.x;
    const int lane = tid & 31;
    const int warp = tid >> 5;
    const int gid  = lane >> 2;
    const int tig  = lane & 3;
    const int tg   = warp & 3;
    const int kg   = warp >> 2;
    const int n    = blockIdx.y;
    const int t0   = blockIdx.x * TT;
    const float* resin = (q == 0) ? x : g_res;
    const float* cbq   = cb + (size_t)q * KC * CD;
    const float* cbnF  = g_cbn2f + q * KC;
    const float* cbT   = g_cbT + (size_t)q * CD * KC;
    const __nv_bfloat16* cbhq = g_cbh + (size_t)q * KC * CD;
    const __nv_bfloat16* cblq = g_cbl + (size_t)q * KC * CD;
    const size_t base  = (size_t)n * CD * TD;
    const size_t abase = ((size_t)n * TD + t0) * CD;
    const unsigned sb  = (unsigned)__cvta_generic_to_shared(dyn);
    if (tid == 0) sCnt = 0;

    auto pf = [&](int s) {
        int kt = s >> 4, cc = s & 15;
        int c0 = cc * 32, k0 = kt * 128;
        unsigned so = sb + (unsigned)((s & 1) * STG);
#pragma unroll
        for (int m = 0; m < 4; m++) {
            int idx = m * 256 + tid;
            int hl  = idx >> 9;
            int row = (idx >> 2) & 127;
            int seg = idx & 3;
            cpa16(so + (hl ? OFF_A_L : OFF_A_H) + row * STRIDE + seg * 16,
                  (hl ? g_xl : g_xh) + abase + (size_t)row * CD + c0 + seg * 8);
            cpa16(so + (hl ? OFF_B_L : OFF_B_H) + row * STRIDE + seg * 16,
                  (hl ? cblq : cbhq) + (size_t)(k0 + row) * CD + c0 + seg * 8);
        }
        cp_commit();
    };

    pf(0); pf(1);

    // S1: strict sequential fp32 chain (reference rounding)
    if (tid < TT) {
        const float* p = resin + base + t0 + tid;
        float s = 0.0f;
        for (int c = 0; c < CD; c++) {
            float v = p[(size_t)c * TD];
            s = __fadd_rn(s, __fmul_rn(v, v));
        }
        sS1[tid] = s;
    }

    float bd1[4], bd2[4]; int bk1[4], bk2[4];
#pragma unroll
    for (int sl = 0; sl < 4; sl++) {
        bd1[sl] = __int_as_float(0x7f800000); bd2[sl] = bd1[sl];
        bk1[sl] = 0; bk2[sl] = 0;
    }
    float d[2][8][4];
#pragma unroll
    for (int mt = 0; mt < 2; mt++)
#pragma unroll
        for (int nt = 0; nt < 8; nt++)
#pragma unroll
            for (int r = 0; r < 4; r++) d[mt][nt][r] = 0.0f;

    // ldmatrix lane-address components
    const unsigned aRow  = (unsigned)(lane & 15);
    const unsigned aColB = (unsigned)((lane >> 4) * 16);
    const unsigned bNtl  = (unsigned)((lane >> 4) & 1);
    const unsigned bRow  = (unsigned)(lane & 7);
    const unsigned bColB = (unsigned)(((lane >> 3) & 1) * 16);

    // ---- HMMA mainloop: 64 steps = 4 kt x 16 c-chunks of 32 ----
    for (int s = 0; s < 64; s++) {
        asm volatile("cp.async.wait_group 1;");
        __syncthreads();
        const unsigned bufo = sb + (unsigned)((s & 1) * STG);

#pragma unroll
        for (int csi = 0; csi < 2; csi++) {
            const unsigned csB = (unsigned)(csi * 32);

            uint32_t ah[2][4], al[2][4];
#pragma unroll
            for (int mt = 0; mt < 2; mt++) {
                unsigned ra = bufo + OFF_A_H
                            + (unsigned)((tg * 32 + mt * 16) + aRow) * STRIDE
                            + csB + aColB;
                ldsm4(ah[mt], ra);
                ldsm4(al[mt], ra + (OFF_A_L - OFF_A_H));
            }
            uint32_t bh[8][2], bl[8][2];
#pragma unroll
            for (int j = 0; j < 4; j++) {
                unsigned ntl = (unsigned)(2 * j) + bNtl;
                unsigned rb  = bufo + OFF_B_H
                             + (unsigned)(kg * 64 + ntl * 8 + bRow) * STRIDE
                             + csB + bColB;
                uint32_t r4[4];
                ldsm4(r4, rb);
                bh[2*j][0] = r4[0]; bh[2*j][1] = r4[1];
                bh[2*j+1][0] = r4[2]; bh[2*j+1][1] = r4[3];
                ldsm4(r4, rb + (OFF_B_L - OFF_B_H));
                bl[2*j][0] = r4[0]; bl[2*j][1] = r4[1];
                bl[2*j+1][0] = r4[2]; bl[2*j+1][1] = r4[3];
            }
            // product-outer ordering: no back-to-back dependent MMAs on one
            // accumulator — 16 independent groups between dependent pairs
#pragma unroll
            for (int p = 0; p < 3; p++)
#pragma unroll
                for (int nt = 0; nt < 8; nt++)
#pragma unroll
                    for (int mt = 0; mt < 2; mt++) {
                        const uint32_t* A = (p == 2) ? al[mt] : ah[mt];
                        uint32_t B0 = (p == 1) ? bl[nt][0] : bh[nt][0];
                        uint32_t B1 = (p == 1) ? bl[nt][1] : bh[nt][1];
                        mma_bf16(d[mt][nt], A, B0, B1);
                        // ll dropped: |sum al*bl| ~2e-5 << tau, rescue covers it
                    }
        }
        __syncthreads();
        if (s + 2 < 64) pf(s + 2); else cp_commit();

        if ((s & 15) == 15) {
            int kt = s >> 4;
#pragma unroll
            for (int mt = 0; mt < 2; mt++)
#pragma unroll
                for (int h = 0; h < 2; h++) {
                    int slot = mt * 2 + h;
                    int tok  = tg * 32 + mt * 16 + h * 8 + gid;
                    float s1v = sS1[tok];
#pragma unroll
                    for (int nt = 0; nt < 8; nt++)
#pragma unroll
                        for (int e = 0; e < 2; e++) {
                            int k = kt * 128 + kg * 64 + nt * 8 + tig * 2 + e;
                            float da = __fmaf_rn(-2.0f, d[mt][nt][h * 2 + e], cbnF[k]) + s1v;
                            merge2(da, k, bd1[slot], bk1[slot], bd2[slot], bk2[slot]);
                            d[mt][nt][h * 2 + e] = 0.0f;
                        }
                }
        }
    }
    asm volatile("cp.async.wait_group 0;");
    __syncthreads();

    // ---- cross-thread top-2 reduce ----
    float* eD1 = (float*)dyn;
    float* eD2 = (float*)(dyn + 4096);
    int*   eK1 = (int*)(dyn + 8192);
    int*   eK2 = (int*)(dyn + 12288);
    {
        int g = tig * 2 + kg;
#pragma unroll
        for (int mt = 0; mt < 2; mt++)
#pragma unroll
            for (int h = 0; h < 2; h++) {
                int slot = mt * 2 + h;
                int tok  = tg * 32 + mt * 16 + h * 8 + gid;
                eD1[g * TT + tok] = bd1[slot]; eK1[g * TT + tok] = bk1[slot];
                eD2[g * TT + tok] = bd2[slot]; eK2[g * TT + tok] = bk2[slot];
            }
    }
    __syncthreads();
    if (tid < TT) {
        float D1 = __int_as_float(0x7f800000), D2 = D1;
        int K1 = 0, K2 = 0;
#pragma unroll
        for (int g = 0; g < 8; g++) {
            merge2(eD1[g * TT + tid], eK1[g * TT + tid], D1, K1, D2, K2);
            merge2(eD2[g * TT + tid], eK2[g * TT + tid], D1, K1, D2, K2);
        }
        sK[tid] = K1;
        float tau = 2e-6f * (sS1[tid] + 512.0f) + 4e-5f;
        if (D2 - D1 < tau) {
            int slot = atomicAdd(&sCnt, 1);
            sList[slot] = tid;
        }
    }
    __syncthreads();

    // ---- exact rescan of flagged tokens (reference fp32 chain) ----
    // g_cbT gives coalesced k-major reads; values bit-identical to cbq[k][c],
    // per-thread chain order unchanged => identical results, 30x fewer wavefronts.
    {
        int cnt = sCnt;
        for (int e = 0; e < cnt; e++) {
            int tl = sList[e];
            const float* xp = resin + base + t0 + tl;
            float a0 = 0.0f, a1 = 0.0f;
            for (int c = 0; c < CD; c++) {
                float xv = xp[(size_t)c * TD];
                const float* row = cbT + (size_t)c * KC;
                a0 = __fmaf_rn(row[tid],       xv, a0);
                a1 = __fmaf_rn(row[tid + 256], xv, a1);
            }
            float S = sS1[tl];
            float d0 = __fadd_rn(__fsub_rn(S, __fmul_rn(2.0f, a0)), cbnF[tid]);
            float d1 = __fadd_rn(__fsub_rn(S, __fmul_rn(2.0f, a1)), cbnF[tid + 256]);
            float bdv = d0; int bkv = tid;
            if (d1 < bdv) { bdv = d1; bkv = tid + 256; }
            sRd[tid] = bdv; sRk[tid] = bkv;
            __syncthreads();
            for (int off = 128; off > 0; off >>= 1) {
                if (tid < off) {
                    float od = sRd[tid + off]; int ok = sRk[tid + off];
                    if (od < sRd[tid] || (od == sRd[tid] && ok < sRk[tid])) {
                        sRd[tid] = od; sRk[tid] = ok;
                    }
                }
                __syncthreads();
            }
            if (tid == 0) sK[tl] = sRk[0];
            __syncthreads();
        }
    }

    // ---- indices + histogram ----
    if (tid < TT) {
        int K = sK[tid];
        out[IDX_OFF + ((size_t)(n * TD + t0 + tid)) * QL + q] = (float)K;
        atomicAdd(&g_hist[q * KC + K], 1u);
    }

    // ---- gather + update (reference fp32 chain) + next-layer bf16 split ----
    float* cbS = (float*)dyn;                  // [128][65]
    const int tl   = tid & 127;
    const int half = tid >> 7;
    double lacc = 0.0;
    for (int ch = 0; ch < 8; ch++) {
        const int c0 = ch * 64;
        __syncthreads();
        for (int u = 0; u < 16; u++) {
            int tt = warp * 16 + u;
            const float* cr = cbq + (size_t)sK[tt] * CD + c0;
            cbS[tt * 65 + lane]      = cr[lane];
            cbS[tt * 65 + lane + 32] = cr[lane + 32];
        }
        __syncthreads();
#pragma unroll
        for (int gph = 0; gph < 4; gph++) {
            unsigned hw[4] = {0, 0, 0, 0}, lw[4] = {0, 0, 0, 0};
            int cb0 = c0 + half * 32 + gph * 8;
#pragma unroll
            for (int e = 0; e < 8; e++) {
                int c = cb0 + e;
                size_t off = base + (size_t)c * TD + t0 + tl;
                float xf = resin[off];
                float xd = cbS[tl * 65 + (c - c0)];
                float qv = __fadd_rn(xf, __fsub_rn(xd, xf));
                float df = __fsub_rn(xf, xd);
                lacc += (double)__fmul_rn(df, df);
                float qa = (q == 0) ? qv : __fadd_rn(g_quant[off], qv);
                if (q < QL - 1) {
                    float rn = __fsub_rn(xf, qv);
                    g_res[off]   = rn;
                    g_quant[off] = qa;
                    __nv_bfloat16 h = __float2bfloat16(rn);
                    __nv_bfloat16 l = __float2bfloat16(rn - __bfloat162float(h));
                    hw[e >> 1] |= (unsigned)__bfloat16_as_ushort(h) << ((e & 1) * 16);
                    lw[e >> 1] |= (unsigned)__bfloat16_as_ushort(l) << ((e & 1) * 16);
                } else {
                    out[off] = qa;
                }
            }
            if (q < QL - 1) {
                size_t ao = abase + (size_t)tl * CD + cb0;
                *(uint4*)(g_xh + ao) = make_uint4(hw[0], hw[1], hw[2], hw[3]);
                *(uint4*)(g_xl + ao) = make_uint4(lw[0], lw[1], lw[2], lw[3]);
            }
        }
    }

    // ---- deterministic block loss partial ----
    for (int o = 16; o > 0; o >>= 1) lacc += __shfl_down_sync(0xffffffffu, lacc, o);
    if (lane == 0) sL[warp] = lacc;
    __syncthreads();
    if (tid == 0) {
        double s = 0.0;
        for (int w = 0; w < 8; w++) s += sL[w];
        g_lossPart[q * 512 + blockIdx.y * 16 + blockIdx.x] = s;
    }
}

// ---- scalars: commit loss mean + perplexity ----
__global__ void vq_final(float* out) {
    __shared__ double sPerp[QL], sLoss[QL];
    int warp = threadIdx.x >> 5, lane = threadIdx.x & 31;
    if (warp < QL) {
        int q = warp;
        double ls = 0.0;
        for (int b = lane; b < 512; b += 32) ls += g_lossPart[q * 512 + b];
        double ent = 0.0;
        for (int k = lane; k < KC; k += 32) {
            float cnt  = (float)g_hist[q * KC + k];
            float prob = cnt / 65536.0f;
            ent += (double)prob * log((double)prob + 1e-7);
        }
        for (int o = 16; o > 0; o >>= 1) {
            ls  += __shfl_down_sync(0xffffffffu, ls, o);
            ent += __shfl_down_sync(0xffffffffu, ent, o);
        }
        if (lane == 0) { sLoss[q] = ls / (double)ELEMS; sPerp[q] = exp(-ent); }
    }
    __syncthreads();
    if (threadIdx.x == 0) {
        double lsum = 0.0, psum = 0.0;
        for (int q = 0; q < QL; q++) { lsum += sLoss[q]; psum += sPerp[q]; }
        out[SCAL_OFF]     = (float)(lsum / (double)QL);
        out[SCAL_OFF + 1] = (float)(psum / (double)QL);
    }
}

extern "C" void kernel_launch(void* const* d_in, const int* in_sizes, int n_in,
                              void* d_out, int out_size) {
    const float* x  = (const float*)d_in[0];   // [32, 512, 2048] f32
    const float* cb = (const float*)d_in[1];   // [6, 512, 512]  f32
    float* out = (float*)d_out;

    cudaFuncSetAttribute(vq_layer,
                         cudaFuncAttributeMaxDynamicSharedMemorySize, DYN_BYTES);

    vq_prep<<<12, 256>>>(cb);
    vq_tr<<<dim3(16, 16, QL), dim3(32, 8)>>>(cb);
    vq_convx<<<dim3(16, 32), 128>>>(x);
    dim3 grid(TD / TT, NB);                    // (16, 32) = 512 blocks
    for (int q = 0; q < QL; q++)
        vq_layer<<<grid, 256, DYN_BYTES>>>(x, cb, out, q);
    vq_final<<<1, QL * 32>>>(out);
}

// round 15
// speedup vs baseline: 1.6326x; 1.2407x over previous
#include <cuda_runtime.h>
#include <cuda_bf16.h>
#include <math.h>
#include <stdint.h>

// Problem shape
#define NB 32
#define CD 512
#define TD 2048
#define KC 512
#define QL 6
#define TT 128

#define ELEMS    33554432ULL
#define IDX_OFF  33554432ULL
#define SCAL_OFF 33947648ULL

// GEMM smem geometry: per stage, 4 panels of 128 rows x 32 bf16 (64B + 16B pad)
#define STRIDE   80
#define OFF_A_H  0
#define OFF_A_L  10240
#define OFF_B_H  20480
#define OFF_B_L  30720
#define STG      40960
#define DYN_BYTES (2 * STG)                   // 81920 B, 2 CTAs/SM

// Device scratch (allocation-free rule)
__device__ float         g_res  [NB * CD * TD];
__device__ float         g_quant[NB * CD * TD];
__device__ __nv_bfloat16 g_xh   [NB * TD * CD];   // residual bf16 hi, [n][t][c]
__device__ __nv_bfloat16 g_xl   [NB * TD * CD];   // residual bf16 lo
__device__ __nv_bfloat16 g_cbh  [QL * KC * CD];
__device__ __nv_bfloat16 g_cbl  [QL * KC * CD];
__device__ float         g_cbT  [QL * CD * KC];   // fp32 codebook transposed [q][c][k]
__device__ float         g_cbn2f[QL * KC];
__device__ float         g_S1   [NB * TD];        // per-token ||res||^2 (exact chain)
__device__ int           g_code [NB * TD];        // per-token selected code
__device__ unsigned int  g_hist [QL * KC];
__device__ double        g_lossPart[QL * 512];

// ---- helpers -------------------------------------------------------------
__device__ __forceinline__ void cpa16(unsigned dst, const void* src) {
    asm volatile("cp.async.cg.shared.global [%0], [%1], 16;" :: "r"(dst), "l"(src));
}
__device__ __forceinline__ void cp_commit() { asm volatile("cp.async.commit_group;"); }

// bf16 HMMA m16n8k16 (plain sm_80+ PTX — NOT arch-"a" gated, unlike tcgen05)
__device__ __forceinline__ void mma_bf16(float* d, const uint32_t* a,
                                         uint32_t b0, uint32_t b1) {
    asm volatile(
        "mma.sync.aligned.m16n8k16.row.col.f32.bf16.bf16.f32 "
        "{%0,%1,%2,%3},{%4,%5,%6,%7},{%8,%9},{%0,%1,%2,%3};"
        : "+f"(d[0]), "+f"(d[1]), "+f"(d[2]), "+f"(d[3])
        : "r"(a[0]), "r"(a[1]), "r"(a[2]), "r"(a[3]), "r"(b0), "r"(b1));
}

// ldmatrix x4 (sm_75+)
__device__ __forceinline__ void ldsm4(uint32_t* r, unsigned a) {
    asm volatile("ldmatrix.sync.aligned.m8n8.x4.shared.b16 {%0,%1,%2,%3}, [%4];"
                 : "=r"(r[0]), "=r"(r[1]), "=r"(r[2]), "=r"(r[3]) : "r"(a));
}

__device__ __forceinline__ void merge2(float v, int k,
                                       float& D1, int& K1, float& D2, int& K2) {
    if (v < D1 || (v == D1 && k < K1)) { D2 = D1; K2 = K1; D1 = v; K1 = k; }
    else if (v < D2 || (v == D2 && k < K2)) { D2 = v; K2 = k; }
}

// ---- prep: hist zero, sequential-fp32 codebook norms, bf16 hi/lo split ----
__global__ void vq_prep(const float* cb) {
    int gid = blockIdx.x * 256 + threadIdx.x;
    if (gid < QL * KC) {
        g_hist[gid] = 0u;
        const float* row = cb + (size_t)gid * CD;
        __nv_bfloat16* ph = g_cbh + (size_t)gid * CD;
        __nv_bfloat16* pl = g_cbl + (size_t)gid * CD;
        float s = 0.0f;
        for (int c = 0; c < CD; c++) {
            float v = row[c];
            s = __fadd_rn(s, __fmul_rn(v, v));
            __nv_bfloat16 h = __float2bfloat16(v);
            ph[c] = h;
            pl[c] = __float2bfloat16(v - __bfloat162float(h));
        }
        g_cbn2f[gid] = s;
    }
}

// ---- coalesced codebook transpose: g_cbT[q][c][k] = cb[q][k][c] ----
__global__ void vq_tr(const float* cb) {
    __shared__ float tile[32][33];
    int q  = blockIdx.z;
    int k0 = blockIdx.x * 32, c0 = blockIdx.y * 32;
    const float* src = cb + (size_t)q * KC * CD;
    for (int i = threadIdx.y; i < 32; i += 8)
        tile[i][threadIdx.x] = src[(size_t)(k0 + i) * CD + c0 + threadIdx.x];
    __syncthreads();
    float* dst = g_cbT + (size_t)q * CD * KC;
    for (int i = threadIdx.y; i < 32; i += 8)
        dst[(size_t)(c0 + i) * KC + k0 + threadIdx.x] = tile[threadIdx.x][i];
}

// ---- layer-0 A split + S1: x -> g_xh/g_xl ([n][t][c]), g_S1 (exact chain) ----
__global__ void vq_convx(const float* x) {
    int n = blockIdx.y, t = blockIdx.x * 128 + threadIdx.x;
    const float* p = x + (size_t)n * CD * TD + t;
    size_t ao = ((size_t)n * TD + t) * CD;
    float s1 = 0.0f;
    for (int g = 0; g < 64; g++) {
        unsigned hw[4], lw[4];
#pragma unroll
        for (int e2 = 0; e2 < 4; e2++) {
            float v0 = p[(size_t)(g * 8 + e2 * 2) * TD];
            float v1 = p[(size_t)(g * 8 + e2 * 2 + 1) * TD];
            s1 = __fadd_rn(s1, __fmul_rn(v0, v0));   // c ascending
            s1 = __fadd_rn(s1, __fmul_rn(v1, v1));
            __nv_bfloat16 h0 = __float2bfloat16(v0), h1 = __float2bfloat16(v1);
            __nv_bfloat16 l0 = __float2bfloat16(v0 - __bfloat162float(h0));
            __nv_bfloat16 l1 = __float2bfloat16(v1 - __bfloat162float(h1));
            hw[e2] = (unsigned)__bfloat16_as_ushort(h0) | ((unsigned)__bfloat16_as_ushort(h1) << 16);
            lw[e2] = (unsigned)__bfloat16_as_ushort(l0) | ((unsigned)__bfloat16_as_ushort(l1) << 16);
        }
        *(uint4*)(g_xh + ao + g * 8) = make_uint4(hw[0], hw[1], hw[2], hw[3]);
        *(uint4*)(g_xl + ao + g * 8) = make_uint4(lw[0], lw[1], lw[2], lw[3]);
    }
    g_S1[(size_t)n * TD + t] = s1;
}

// ---- assign kernel: pipelined HMMA GEMM + top-2 + rescan + indices ----
__global__ void __launch_bounds__(256, 2) vq_assign(
    const float* x, const float* cb, float* out, int q)
{
    extern __shared__ char dyn[];
    __shared__ float  sS1[TT];
    __shared__ int    sK[TT];
    __shared__ int    sList[TT];
    __shared__ int    sCnt;
    __shared__ float  sRd[256];
    __shared__ int    sRk[256];

    const int tid  = threadIdx.x;
    const int lane = tid & 31;
    const int warp = tid >> 5;
    const int gid  = lane >> 2;
    const int tig  = lane & 3;
    const int tg   = warp & 3;
    const int kg   = warp >> 2;
    const int n    = blockIdx.y;
    const int t0   = blockIdx.x * TT;
    const float* resin = (q == 0) ? x : g_res;
    const float* cbnF  = g_cbn2f + q * KC;
    const float* cbT   = g_cbT + (size_t)q * CD * KC;
    const __nv_bfloat16* cbhq = g_cbh + (size_t)q * KC * CD;
    const __nv_bfloat16* cblq = g_cbl + (size_t)q * KC * CD;
    const size_t base  = (size_t)n * CD * TD;
    const size_t abase = ((size_t)n * TD + t0) * CD;
    const unsigned sb  = (unsigned)__cvta_generic_to_shared(dyn);
    if (tid == 0) sCnt = 0;
    if (tid < TT) sS1[tid] = g_S1[(size_t)n * TD + t0 + tid];

    auto pf = [&](int s) {
        int kt = s >> 4, cc = s & 15;
        int c0 = cc * 32, k0 = kt * 128;
        unsigned so = sb + (unsigned)((s & 1) * STG);
#pragma unroll
        for (int m = 0; m < 4; m++) {
            int idx = m * 256 + tid;
            int hl  = idx >> 9;
            int row = (idx >> 2) & 127;
            int seg = idx & 3;
            cpa16(so + (hl ? OFF_A_L : OFF_A_H) + row * STRIDE + seg * 16,
                  (hl ? g_xl : g_xh) + abase + (size_t)row * CD + c0 + seg * 8);
            cpa16(so + (hl ? OFF_B_L : OFF_B_H) + row * STRIDE + seg * 16,
                  (hl ? cblq : cbhq) + (size_t)(k0 + row) * CD + c0 + seg * 8);
        }
        cp_commit();
    };

    pf(0); pf(1);

    float bd1[4], bd2[4]; int bk1[4], bk2[4];
#pragma unroll
    for (int sl = 0; sl < 4; sl++) {
        bd1[sl] = __int_as_float(0x7f800000); bd2[sl] = bd1[sl];
        bk1[sl] = 0; bk2[sl] = 0;
    }
    float d[2][8][4];
#pragma unroll
    for (int mt = 0; mt < 2; mt++)
#pragma unroll
        for (int nt = 0; nt < 8; nt++)
#pragma unroll
            for (int r = 0; r < 4; r++) d[mt][nt][r] = 0.0f;

    const unsigned aRow  = (unsigned)(lane & 15);
    const unsigned aColB = (unsigned)((lane >> 4) * 16);
    const unsigned bNtl  = (unsigned)((lane >> 4) & 1);
    const unsigned bRow  = (unsigned)(lane & 7);
    const unsigned bColB = (unsigned)(((lane >> 3) & 1) * 16);

    for (int s = 0; s < 64; s++) {
        asm volatile("cp.async.wait_group 1;");
        __syncthreads();
        const unsigned bufo = sb + (unsigned)((s & 1) * STG);

#pragma unroll
        for (int csi = 0; csi < 2; csi++) {
            const unsigned csB = (unsigned)(csi * 32);
            uint32_t ah[2][4], al[2][4];
#pragma unroll
            for (int mt = 0; mt < 2; mt++) {
                unsigned ra = bufo + OFF_A_H
                            + (unsigned)((tg * 32 + mt * 16) + aRow) * STRIDE
                            + csB + aColB;
                ldsm4(ah[mt], ra);
                ldsm4(al[mt], ra + (OFF_A_L - OFF_A_H));
            }
            uint32_t bh[8][2], bl[8][2];
#pragma unroll
            for (int j = 0; j < 4; j++) {
                unsigned ntl = (unsigned)(2 * j) + bNtl;
                unsigned rb  = bufo + OFF_B_H
                             + (unsigned)(kg * 64 + ntl * 8 + bRow) * STRIDE
                             + csB + bColB;
                uint32_t r4[4];
                ldsm4(r4, rb);
                bh[2*j][0] = r4[0]; bh[2*j][1] = r4[1];
                bh[2*j+1][0] = r4[2]; bh[2*j+1][1] = r4[3];
                ldsm4(r4, rb + (OFF_B_L - OFF_B_H));
                bl[2*j][0] = r4[0]; bl[2*j][1] = r4[1];
                bl[2*j+1][0] = r4[2]; bl[2*j+1][1] = r4[3];
            }
#pragma unroll
            for (int p = 0; p < 3; p++)
#pragma unroll
                for (int nt = 0; nt < 8; nt++)
#pragma unroll
                    for (int mt = 0; mt < 2; mt++) {
                        const uint32_t* A = (p == 2) ? al[mt] : ah[mt];
                        uint32_t B0 = (p == 1) ? bl[nt][0] : bh[nt][0];
                        uint32_t B1 = (p == 1) ? bl[nt][1] : bh[nt][1];
                        mma_bf16(d[mt][nt], A, B0, B1);
                        // ll dropped: |sum al*bl| ~2e-5 << tau, rescue covers it
                    }
        }
        __syncthreads();
        if (s + 2 < 64) pf(s + 2); else cp_commit();

        if ((s & 15) == 15) {
            int kt = s >> 4;
#pragma unroll
            for (int mt = 0; mt < 2; mt++)
#pragma unroll
                for (int h = 0; h < 2; h++) {
                    int slot = mt * 2 + h;
                    int tok  = tg * 32 + mt * 16 + h * 8 + gid;
                    float s1v = sS1[tok];
#pragma unroll
                    for (int nt = 0; nt < 8; nt++)
#pragma unroll
                        for (int e = 0; e < 2; e++) {
                            int k = kt * 128 + kg * 64 + nt * 8 + tig * 2 + e;
                            float da = __fmaf_rn(-2.0f, d[mt][nt][h * 2 + e], cbnF[k]) + s1v;
                            merge2(da, k, bd1[slot], bk1[slot], bd2[slot], bk2[slot]);
                            d[mt][nt][h * 2 + e] = 0.0f;
                        }
                }
        }
    }
    asm volatile("cp.async.wait_group 0;");
    __syncthreads();

    // ---- cross-thread top-2 reduce ----
    float* eD1 = (float*)dyn;
    float* eD2 = (float*)(dyn + 4096);
    int*   eK1 = (int*)(dyn + 8192);
    int*   eK2 = (int*)(dyn + 12288);
    {
        int g = tig * 2 + kg;
#pragma unroll
        for (int mt = 0; mt < 2; mt++)
#pragma unroll
            for (int h = 0; h < 2; h++) {
                int slot = mt * 2 + h;
                int tok  = tg * 32 + mt * 16 + h * 8 + gid;
                eD1[g * TT + tok] = bd1[slot]; eK1[g * TT + tok] = bk1[slot];
                eD2[g * TT + tok] = bd2[slot]; eK2[g * TT + tok] = bk2[slot];
            }
    }
    __syncthreads();
    if (tid < TT) {
        float D1 = __int_as_float(0x7f800000), D2 = D1;
        int K1 = 0, K2 = 0;
#pragma unroll
        for (int g = 0; g < 8; g++) {
            merge2(eD1[g * TT + tid], eK1[g * TT + tid], D1, K1, D2, K2);
            merge2(eD2[g * TT + tid], eK2[g * TT + tid], D1, K1, D2, K2);
        }
        sK[tid] = K1;
        float tau = 2e-6f * (sS1[tid] + 512.0f) + 4e-5f;
        if (D2 - D1 < tau) {
            int slot = atomicAdd(&sCnt, 1);
            sList[slot] = tid;
        }
    }
    __syncthreads();

    // ---- exact rescan of flagged tokens (reference fp32 chain, coalesced) ----
    {
        int cnt = sCnt;
        for (int e = 0; e < cnt; e++) {
            int tl = sList[e];
            const float* xp = resin + base + t0 + tl;
            float a0 = 0.0f, a1 = 0.0f;
            for (int c = 0; c < CD; c++) {
                float xv = xp[(size_t)c * TD];
                const float* row = cbT + (size_t)c * KC;
                a0 = __fmaf_rn(row[tid],       xv, a0);
                a1 = __fmaf_rn(row[tid + 256], xv, a1);
            }
            float S = sS1[tl];
            float d0 = __fadd_rn(__fsub_rn(S, __fmul_rn(2.0f, a0)), cbnF[tid]);
            float d1 = __fadd_rn(__fsub_rn(S, __fmul_rn(2.0f, a1)), cbnF[tid + 256]);
            float bdv = d0; int bkv = tid;
            if (d1 < bdv) { bdv = d1; bkv = tid + 256; }
            sRd[tid] = bdv; sRk[tid] = bkv;
            __syncthreads();
            for (int off = 128; off > 0; off >>= 1) {
                if (tid < off) {
                    float od = sRd[tid + off]; int ok = sRk[tid + off];
                    if (od < sRd[tid] || (od == sRd[tid] && ok < sRk[tid])) {
                        sRd[tid] = od; sRk[tid] = ok;
                    }
                }
                __syncthreads();
            }
            if (tid == 0) sK[tl] = sRk[0];
            __syncthreads();
        }
    }

    // ---- indices + histogram + code handoff ----
    if (tid < TT) {
        int K = sK[tid];
        g_code[(size_t)n * TD + t0 + tid] = K;
        out[IDX_OFF + ((size_t)(n * TD + t0 + tid)) * QL + q] = (float)K;
        atomicAdd(&g_hist[q * KC + K], 1u);
    }
}

// ---- apply kernel (high occupancy): gather + update + split + S1(next) ----
__global__ void __launch_bounds__(256, 5) vq_apply(
    const float* x, const float* cb, float* out, int q)
{
    __shared__ float  cbS[TT * 65];
    __shared__ int    sK[TT];
    __shared__ double sL[8];

    const int tid  = threadIdx.x;
    const int lane = tid & 31;
    const int warp = tid >> 5;
    const int n    = blockIdx.y;
    const int t0   = blockIdx.x * TT;
    const float* resin = (q == 0) ? x : g_res;
    const float* cbq   = cb + (size_t)q * KC * CD;
    const size_t base  = (size_t)n * CD * TD;
    const size_t abase = ((size_t)n * TD + t0) * CD;

    if (tid < TT) sK[tid] = g_code[(size_t)n * TD + t0 + tid];
    __syncthreads();

    const int tl   = tid & 127;
    const int half = tid >> 7;
    double lacc = 0.0;
    for (int ch = 0; ch < 8; ch++) {
        const int c0 = ch * 64;
        if (ch) __syncthreads();                // protect cbS reuse
        for (int u = 0; u < 16; u++) {
            int tt = warp * 16 + u;
            const float* cr = cbq + (size_t)sK[tt] * CD + c0;
            cbS[tt * 65 + lane]      = cr[lane];
            cbS[tt * 65 + lane + 32] = cr[lane + 32];
        }
        __syncthreads();
#pragma unroll
        for (int gph = 0; gph < 4; gph++) {
            unsigned hw[4] = {0, 0, 0, 0}, lw[4] = {0, 0, 0, 0};
            int cb0 = c0 + half * 32 + gph * 8;
#pragma unroll
            for (int e = 0; e < 8; e++) {
                int c = cb0 + e;
                size_t off = base + (size_t)c * TD + t0 + tl;
                float xf = resin[off];
                float xd = cbS[tl * 65 + (c - c0)];
                float qv = __fadd_rn(xf, __fsub_rn(xd, xf));   // straight-through
                float df = __fsub_rn(xf, xd);
                lacc += (double)__fmul_rn(df, df);
                float qa = (q == 0) ? qv : __fadd_rn(g_quant[off], qv);
                if (q < QL - 1) {
                    float rn = __fsub_rn(xf, qv);
                    g_res[off]   = rn;
                    g_quant[off] = qa;
                    __nv_bfloat16 h = __float2bfloat16(rn);
                    __nv_bfloat16 l = __float2bfloat16(rn - __bfloat162float(h));
                    hw[e >> 1] |= (unsigned)__bfloat16_as_ushort(h) << ((e & 1) * 16);
                    lw[e >> 1] |= (unsigned)__bfloat16_as_ushort(l) << ((e & 1) * 16);
                } else {
                    out[off] = qa;
                }
            }
            if (q < QL - 1) {
                size_t ao = abase + (size_t)tl * CD + cb0;
                *(uint4*)(g_xh + ao) = make_uint4(hw[0], hw[1], hw[2], hw[3]);
                *(uint4*)(g_xl + ao) = make_uint4(lw[0], lw[1], lw[2], lw[3]);
            }
        }
    }

    // ---- deterministic block loss partial ----
    for (int o = 16; o > 0; o >>= 1) lacc += __shfl_down_sync(0xffffffffu, lacc, o);
    if (lane == 0) sL[warp] = lacc;
    __syncthreads();
    if (tid == 0) {
        double s = 0.0;
        for (int w = 0; w < 8; w++) s += sL[w];
        g_lossPart[q * 512 + blockIdx.y * 16 + blockIdx.x] = s;
    }

    // ---- S1 for next layer: strict sequential fp32 chain over new residual ----
    if (q < QL - 1 && tid < TT) {
        const float* p = g_res + base + t0 + tid;   // block-local writes, post-barrier
        float s = 0.0f;
        for (int c = 0; c < CD; c++) {
            float v = p[(size_t)c * TD];
            s = __fadd_rn(s, __fmul_rn(v, v));
        }
        g_S1[(size_t)n * TD + t0 + tid] = s;
    }
}

// ---- scalars: commit loss mean + perplexity ----
__global__ void vq_final(float* out) {
    __shared__ double sPerp[QL], sLoss[QL];
    int warp = threadIdx.x >> 5, lane = threadIdx.x & 31;
    if (warp < QL) {
        int q = warp;
        double ls = 0.0;
        for (int b = lane; b < 512; b += 32) ls += g_lossPart[q * 512 + b];
        double ent = 0.0;
        for (int k = lane; k < KC; k += 32) {
            float cnt  = (float)g_hist[q * KC + k];
            float prob = cnt / 65536.0f;
            ent += (double)prob * log((double)prob + 1e-7);
        }
        for (int o = 16; o > 0; o >>= 1) {
            ls  += __shfl_down_sync(0xffffffffu, ls, o);
            ent += __shfl_down_sync(0xffffffffu, ent, o);
        }
        if (lane == 0) { sLoss[q] = ls / (double)ELEMS; sPerp[q] = exp(-ent); }
    }
    __syncthreads();
    if (threadIdx.x == 0) {
        double lsum = 0.0, psum = 0.0;
        for (int q = 0; q < QL; q++) { lsum += sLoss[q]; psum += sPerp[q]; }
        out[SCAL_OFF]     = (float)(lsum / (double)QL);
        out[SCAL_OFF + 1] = (float)(psum / (double)QL);
    }
}

extern "C" void kernel_launch(void* const* d_in, const int* in_sizes, int n_in,
                              void* d_out, int out_size) {
    const float* x  = (const float*)d_in[0];   // [32, 512, 2048] f32
    const float* cb = (const float*)d_in[1];   // [6, 512, 512]  f32
    float* out = (float*)d_out;

    cudaFuncSetAttribute(vq_assign,
                         cudaFuncAttributeMaxDynamicSharedMemorySize, DYN_BYTES);

    vq_prep<<<12, 256>>>(cb);
    vq_tr<<<dim3(16, 16, QL), dim3(32, 8)>>>(cb);
    vq_convx<<<dim3(16, 32), 128>>>(x);
    dim3 grid(TD / TT, NB);                    // (16, 32) = 512 blocks
    for (int q = 0; q < QL; q++) {
        vq_assign<<<grid, 256, DYN_BYTES>>>(x, cb, out, q);
        vq_apply <<<grid, 256>>>(x, cb, out, q);
    }
    vq_final<<<1, QL * 32>>>(out);
}